// round 5
// baseline (speedup 1.0000x reference)
#include <cuda_runtime.h>

#define TT 32768      // B*S tokens
#define SS 8192       // sequence length
#define DD 512        // model dim
#define FF 2048       // ffn hidden
#define NM 1024       // concatenated MoE hidden (2 layers * E*H)

#define BM 128
#define BN 256
#define BK 32
#define NSTG 3
#define NTHR 512
#define PADW 36                            // floats per smem row (144B)
#define STG_FLOATS ((BM + BN) * PADW)      // 13824 floats per stage
#define SMEM_BYTES (NSTG * STG_FLOATS * 4) // 165888

// Scratch (device globals; no allocation allowed)
__device__ float g_H1[(unsigned long long)TT * FF];
__device__ float g_Hm[(unsigned long long)TT * NM];
__device__ float g_Xc[(unsigned long long)TT * DD];   // tf32-rounded x
__device__ float g_W1t[FF * DD];     // W1^T  [2048,512] K-major (tf32-rounded)
__device__ float g_W2t[DD * FF];     // W2^T  [512,2048] K-major
__device__ float g_WaTt[NM * DD];    // MoE up weights [1024,512] K-major
__device__ float g_Wbt[DD * NM];     // MoE down weights [512,1024] K-major
__device__ float g_w[TT * 16];       // dense gate weights

__device__ __forceinline__ float gelu_f(float x) {
    float x3 = x * x * x;
    float t = tanhf(0.7978845608028654f * (x + 0.044715f * x3));
    return 0.5f * x * (1.0f + t);
}
__device__ __forceinline__ float f2tf_f(float x) {
    float d;
    asm("cvt.rna.tf32.f32 %0, %1;" : "=f"(d) : "f"(x));
    return d;
}
__device__ __forceinline__ void cp16(unsigned dst, const void* src) {
    asm volatile("cp.async.cg.shared.global [%0], [%1], 16;" :: "r"(dst), "l"(src) : "memory");
}
__device__ __forceinline__ void ldsm4(unsigned& r0, unsigned& r1, unsigned& r2, unsigned& r3,
                                      unsigned addr) {
    asm volatile("ldmatrix.sync.aligned.m8n8.x4.shared.b16 {%0,%1,%2,%3}, [%4];"
                 : "=r"(r0), "=r"(r1), "=r"(r2), "=r"(r3) : "r"(addr));
}
__device__ __forceinline__ void mma_tf32(float* c, const unsigned* a, const unsigned* b) {
    asm volatile(
        "mma.sync.aligned.m16n8k8.row.col.f32.tf32.tf32.f32 "
        "{%0,%1,%2,%3}, {%4,%5,%6,%7}, {%8,%9}, {%0,%1,%2,%3};"
        : "+f"(c[0]), "+f"(c[1]), "+f"(c[2]), "+f"(c[3])
        : "r"(a[0]), "r"(a[1]), "r"(a[2]), "r"(a[3]), "r"(b[0]), "r"(b[1]));
}

// ---------------------------------------------------------------------------
// Prep: weight repacks (K-major, tf32-rounded) + x rounding
// ---------------------------------------------------------------------------
__global__ void prep_x(const float* __restrict__ x) {
    int i = blockIdx.x * 256 + threadIdx.x;
    float4 v = ((const float4*)x)[i];
    v.x = f2tf_f(v.x); v.y = f2tf_f(v.y); v.z = f2tf_f(v.z); v.w = f2tf_f(v.w);
    ((float4*)g_Xc)[i] = v;
}
__global__ void prep_w1(const float* __restrict__ W1) {      // [512,2048] -> [2048,512]
    int i = blockIdx.x * 256 + threadIdx.x;
    int n = i >> 9, d = i & 511;
    g_W1t[i] = f2tf_f(W1[d * FF + n]);
}
__global__ void prep_w2(const float* __restrict__ W2) {      // [2048,512] -> [512,2048]
    int i = blockIdx.x * 256 + threadIdx.x;
    int d = i >> 11, f = i & 2047;
    g_W2t[i] = f2tf_f(W2[f * DD + d]);
}
__global__ void prep_wa(const float* __restrict__ Wa1, const float* __restrict__ Wa2) {
    int i = blockIdx.x * 256 + threadIdx.x;                  // -> [1024,512]
    int n = i >> 9, d = i & 511;
    int L = n >> 9, c = n & 511;
    const float* Wa = L ? Wa2 : Wa1;                         // [E,D,H]
    g_WaTt[i] = f2tf_f(Wa[((c >> 6) * DD + d) * 64 + (c & 63)]);
}
__global__ void prep_wb(const float* __restrict__ Wb1, const float* __restrict__ Wb2) {
    int i = blockIdx.x * 256 + threadIdx.x;                  // -> [512,1024]
    int d = i >> 10, j = i & 1023;
    const float* Wb = (j >> 9) ? Wb2 : Wb1;                  // [E,H,D] flat [512,512]
    g_Wbt[i] = f2tf_f(Wb[(j & 511) * DD + d]);
}

// ---------------------------------------------------------------------------
// Gating: one warp per token (on raw fp32 x — routing is bit-exact)
// ---------------------------------------------------------------------------
__device__ __forceinline__ void write_top2(const float* a, float* o) {
    int i0 = 0; float v0 = a[0];
#pragma unroll
    for (int e = 1; e < 8; e++) if (a[e] > v0) { v0 = a[e]; i0 = e; }
    int i1 = -1; float v1 = -3.4e38f;
#pragma unroll
    for (int e = 0; e < 8; e++) if (e != i0 && a[e] > v1) { v1 = a[e]; i1 = e; }
    float t = expf(v1 - v0);
    float inv = 1.0f / (1.0f + t);
#pragma unroll
    for (int e = 0; e < 8; e++) o[e] = 0.0f;
    o[i0] = inv;
    o[i1] = t * inv;
}

__global__ void gate_kernel(const float* __restrict__ x,
                            const float* __restrict__ Wg1,
                            const float* __restrict__ Wg2) {
    int tok = blockIdx.x * 8 + (threadIdx.x >> 5);
    int lane = threadIdx.x & 31;
    if (tok >= TT) return;
    const float* xr = x + (size_t)tok * DD;
    float a1[8], a2[8];
#pragma unroll
    for (int e = 0; e < 8; e++) { a1[e] = 0.0f; a2[e] = 0.0f; }
    for (int j = lane; j < DD; j += 32) {
        float xv = xr[j];
#pragma unroll
        for (int e = 0; e < 8; e++) {
            a1[e] = fmaf(xv, Wg1[j * 8 + e], a1[e]);
            a2[e] = fmaf(xv, Wg2[j * 8 + e], a2[e]);
        }
    }
#pragma unroll
    for (int e = 0; e < 8; e++) {
#pragma unroll
        for (int o = 16; o; o >>= 1) {
            a1[e] += __shfl_xor_sync(0xffffffffu, a1[e], o);
            a2[e] += __shfl_xor_sync(0xffffffffu, a2[e], o);
        }
    }
    if (lane == 0) {
        write_top2(a1, &g_w[tok * 16]);
        write_top2(a2, &g_w[tok * 16 + 8]);
    }
}

// ---------------------------------------------------------------------------
// tf32 mma.sync GEMM: 128x256 tile, BK=32, 3-stage cp.async, 512 threads.
// Operands are pre-rounded to tf32 — mainloop is pure ldmatrix + mma.
// 16 warps in a 4x4 grid; each warp computes 32x64.
// EPI 0: H1 = tf32(gelu(acc + bias))    EPI 1: out = acc + bias
// EPI 2: Hm = tf32(mask * w * gelu(acc)) EPI 3: out += acc (rows s>=id)
// ---------------------------------------------------------------------------
template <int EPI>
__global__ __launch_bounds__(NTHR, 1)
void gemm_mma(const float* __restrict__ A, const float* __restrict__ Bt,
              const float* __restrict__ bias, float* __restrict__ C,
              int K, int ldc, const int* __restrict__ idp)
{
    const int col0 = blockIdx.x * BN;
    const int row0 = blockIdx.y * BM;
    int idv = 0;
    if (EPI >= 2) {
        idv = *idp;
        if ((row0 & (SS - 1)) + BM - 1 < idv) return;   // tile fully masked
    }

    extern __shared__ float sm[];
    const unsigned smb = (unsigned)__cvta_generic_to_shared(sm);
    const int tid  = threadIdx.x;
    const int wid  = tid >> 5;
    const int lane = tid & 31;
    const int KT   = K >> 5;

    const int m0 = (wid >> 2) * 32;     // warp row offset in tile
    const int n0 = (wid & 3) * 64;      // warp col offset in tile

    const unsigned aoff = ((m0 + (lane & 7) + ((lane >> 3) & 1) * 8) * PADW
                           + (lane >> 4) * 4) * 4;
    const unsigned boff = ((BM + n0 + (lane & 7) + ((lane >> 3) & 2) * 4) * PADW
                           + ((lane >> 3) & 1) * 4) * 4;

    float acc[2][8][4];
#pragma unroll
    for (int i = 0; i < 2; i++)
#pragma unroll
        for (int j = 0; j < 8; j++)
#pragma unroll
            for (int r = 0; r < 4; r++) acc[i][j][r] = 0.0f;

    auto load_stage = [&](int st, int k0) {
        unsigned base = smb + (unsigned)(st * STG_FLOATS * 4);
#pragma unroll
        for (int i = 0; i < 6; i++) {
            int cid = tid + i * NTHR;              // 0..3071
            int row = cid >> 3, c = cid & 7;
            unsigned dst = base + (unsigned)(row * PADW + c * 4) * 4;
            const float* src = (row < BM)
                ? A  + (size_t)(row0 + row) * K + k0 + c * 4
                : Bt + (size_t)(col0 + row - BM) * K + k0 + c * 4;
            cp16(dst, src);
        }
        asm volatile("cp.async.commit_group;" ::: "memory");
    };

    load_stage(0, 0);
    if (KT > 1) load_stage(1, BK);

#pragma unroll 1
    for (int kt = 0; kt < KT; kt++) {
        if (kt + 2 < KT) {
            load_stage((kt + 2) % NSTG, (kt + 2) * BK);
            asm volatile("cp.async.wait_group 2;" ::: "memory");
        } else if (kt + 1 < KT) {
            asm volatile("cp.async.wait_group 1;" ::: "memory");
        } else {
            asm volatile("cp.async.wait_group 0;" ::: "memory");
        }
        __syncthreads();

        const unsigned sbase = smb + (unsigned)((kt % NSTG) * STG_FLOATS * 4);
#pragma unroll
        for (int ks = 0; ks < 4; ks++) {
            const unsigned koff = ks * 32;     // 8 tf32 = 32B
            unsigned a[2][4];
#pragma unroll
            for (int mt = 0; mt < 2; mt++)
                ldsm4(a[mt][0], a[mt][1], a[mt][2], a[mt][3],
                      sbase + aoff + (unsigned)(mt * 16 * PADW * 4) + koff);
            unsigned b[8][2];
#pragma unroll
            for (int np = 0; np < 4; np++) {
                unsigned r0, r1, r2, r3;
                ldsm4(r0, r1, r2, r3,
                      sbase + boff + (unsigned)(np * 16 * PADW * 4) + koff);
                b[2*np][0]   = r0; b[2*np][1]   = r1;
                b[2*np+1][0] = r2; b[2*np+1][1] = r3;
            }
#pragma unroll
            for (int mt = 0; mt < 2; mt++)
#pragma unroll
                for (int nt = 0; nt < 8; nt++)
                    mma_tf32(acc[mt][nt], a[mt], b[nt]);
        }
        __syncthreads();
    }

    // ---- epilogue ----
    const int g = lane >> 2, t = lane & 3;
#pragma unroll
    for (int mt = 0; mt < 2; mt++) {
#pragma unroll
        for (int nt = 0; nt < 8; nt++) {
            int r0 = row0 + m0 + mt * 16 + g;
            int r1 = r0 + 8;
            int c  = col0 + n0 + nt * 8 + 2 * t;
            float* p0 = C + (size_t)r0 * ldc + c;
            float* p1 = C + (size_t)r1 * ldc + c;
            float v00 = acc[mt][nt][0], v01 = acc[mt][nt][1];
            float v10 = acc[mt][nt][2], v11 = acc[mt][nt][3];
            if (EPI == 0) {
                float2 bb = *(const float2*)(bias + c);
                float2 o0 = { f2tf_f(gelu_f(v00 + bb.x)), f2tf_f(gelu_f(v01 + bb.y)) };
                float2 o1 = { f2tf_f(gelu_f(v10 + bb.x)), f2tf_f(gelu_f(v11 + bb.y)) };
                *(float2*)p0 = o0; *(float2*)p1 = o1;
            } else if (EPI == 1) {
                float2 bb = *(const float2*)(bias + c);
                float2 o0 = { v00 + bb.x, v01 + bb.y };
                float2 o1 = { v10 + bb.x, v11 + bb.y };
                *(float2*)p0 = o0; *(float2*)p1 = o1;
            } else if (EPI == 2) {
                bool a0 = ((r0 & (SS - 1)) >= idv);
                bool a1 = ((r1 & (SS - 1)) >= idv);
                float w0 = a0 ? g_w[r0 * 16 + (c >> 6)] : 0.0f;
                float w1 = a1 ? g_w[r1 * 16 + (c >> 6)] : 0.0f;
                float2 o0 = { a0 ? f2tf_f(gelu_f(v00) * w0) : 0.0f,
                              a0 ? f2tf_f(gelu_f(v01) * w0) : 0.0f };
                float2 o1 = { a1 ? f2tf_f(gelu_f(v10) * w1) : 0.0f,
                              a1 ? f2tf_f(gelu_f(v11) * w1) : 0.0f };
                *(float2*)p0 = o0; *(float2*)p1 = o1;
            } else {  // EPI == 3
                if ((r0 & (SS - 1)) >= idv) {
                    float2 o = *(const float2*)p0;
                    o.x += v00; o.y += v01;
                    *(float2*)p0 = o;
                }
                if ((r1 & (SS - 1)) >= idv) {
                    float2 o = *(const float2*)p1;
                    o.x += v10; o.y += v11;
                    *(float2*)p1 = o;
                }
            }
        }
    }
}

// ---------------------------------------------------------------------------
extern "C" void kernel_launch(void* const* d_in, const int* in_sizes, int n_in,
                              void* d_out, int out_size) {
    const float* x   = (const float*)d_in[0];
    const int*   idp = (const int*)  d_in[1];
    const float* W1  = (const float*)d_in[2];
    const float* b1  = (const float*)d_in[3];
    const float* W2  = (const float*)d_in[4];
    const float* b2  = (const float*)d_in[5];
    const float* Wg1 = (const float*)d_in[6];
    const float* Wa1 = (const float*)d_in[7];
    const float* Wb1 = (const float*)d_in[8];
    const float* Wg2 = (const float*)d_in[9];
    const float* Wa2 = (const float*)d_in[10];
    const float* Wb2 = (const float*)d_in[11];
    float* out = (float*)d_out;
    (void)in_sizes; (void)n_in; (void)out_size;

    float *H1, *Hm, *Xc, *W1t, *W2t, *WaTt, *Wbt;
    cudaGetSymbolAddress((void**)&H1,   g_H1);
    cudaGetSymbolAddress((void**)&Hm,   g_Hm);
    cudaGetSymbolAddress((void**)&Xc,   g_Xc);
    cudaGetSymbolAddress((void**)&W1t,  g_W1t);
    cudaGetSymbolAddress((void**)&W2t,  g_W2t);
    cudaGetSymbolAddress((void**)&WaTt, g_WaTt);
    cudaGetSymbolAddress((void**)&Wbt,  g_Wbt);

    cudaFuncSetAttribute(gemm_mma<0>, cudaFuncAttributeMaxDynamicSharedMemorySize, SMEM_BYTES);
    cudaFuncSetAttribute(gemm_mma<1>, cudaFuncAttributeMaxDynamicSharedMemorySize, SMEM_BYTES);
    cudaFuncSetAttribute(gemm_mma<2>, cudaFuncAttributeMaxDynamicSharedMemorySize, SMEM_BYTES);
    cudaFuncSetAttribute(gemm_mma<3>, cudaFuncAttributeMaxDynamicSharedMemorySize, SMEM_BYTES);

    // Prep: operand rounding + repack + gating
    prep_x <<<(TT * (DD / 4)) / 256, 256>>>(x);
    prep_w1<<<FF * DD / 256, 256>>>(W1);
    prep_w2<<<DD * FF / 256, 256>>>(W2);
    prep_wa<<<NM * DD / 256, 256>>>(Wa1, Wa2);
    prep_wb<<<DD * NM / 256, 256>>>(Wb1, Wb2);
    gate_kernel<<<TT / 8, 256>>>(x, Wg1, Wg2);

    // FFN: out = gelu(x@W1 + b1) @ W2 + b2
    gemm_mma<0><<<dim3(FF / BN, TT / BM), NTHR, SMEM_BYTES>>>(Xc, W1t, b1, H1,  DD, FF, nullptr);
    gemm_mma<1><<<dim3(DD / BN, TT / BM), NTHR, SMEM_BYTES>>>(H1, W2t, b2, out, FF, DD, nullptr);

    // MoE (both layers fused): only tokens with s >= id do real work
    gemm_mma<2><<<dim3(NM / BN, TT / BM), NTHR, SMEM_BYTES>>>(Xc, WaTt, nullptr, Hm,  DD, NM, idp);
    gemm_mma<3><<<dim3(DD / BN, TT / BM), NTHR, SMEM_BYTES>>>(Hm, Wbt,  nullptr, out, NM, DD, idp);
}

// round 6
// speedup vs baseline: 1.1192x; 1.1192x over previous
#include <cuda_runtime.h>

#define TT 32768      // B*S tokens
#define SS 8192       // sequence length
#define DD 512        // model dim
#define FF 2048       // ffn hidden
#define NM 1024       // concatenated MoE hidden (2 layers * E*H)

#define BM 128
#define BN 128
#define BK 32
#define NSTG 3
#define PADW 36                            // floats per smem row (144B)
#define STG_FLOATS ((BM + BN) * PADW)      // 9216 floats per stage
#define SMEM_BYTES (NSTG * STG_FLOATS * 4) // 110592

// Scratch (device globals; no allocation allowed)
__device__ float g_H1[(unsigned long long)TT * FF];
__device__ float g_Hm[(unsigned long long)TT * NM];
__device__ float g_Xc[(unsigned long long)TT * DD];   // tf32-rounded x
__device__ float g_W1t[FF * DD];     // W1^T  [2048,512] K-major (tf32-rounded)
__device__ float g_W2t[DD * FF];     // W2^T  [512,2048] K-major
__device__ float g_WaTt[NM * DD];    // MoE up weights [1024,512] K-major
__device__ float g_Wbt[DD * NM];     // MoE down weights [512,1024] K-major
__device__ float g_w[TT * 16];       // dense gate weights

__device__ __forceinline__ float gelu_f(float x) {
    float x3 = x * x * x;
    float t = tanhf(0.7978845608028654f * (x + 0.044715f * x3));
    return 0.5f * x * (1.0f + t);
}
__device__ __forceinline__ float f2tf_f(float x) {
    float d;
    asm("cvt.rna.tf32.f32 %0, %1;" : "=f"(d) : "f"(x));
    return d;
}
__device__ __forceinline__ void cp16(unsigned dst, const void* src) {
    asm volatile("cp.async.cg.shared.global [%0], [%1], 16;" :: "r"(dst), "l"(src) : "memory");
}
__device__ __forceinline__ void ldsm4(unsigned& r0, unsigned& r1, unsigned& r2, unsigned& r3,
                                      unsigned addr) {
    asm volatile("ldmatrix.sync.aligned.m8n8.x4.shared.b16 {%0,%1,%2,%3}, [%4];"
                 : "=r"(r0), "=r"(r1), "=r"(r2), "=r"(r3) : "r"(addr));
}
__device__ __forceinline__ void mma_tf32(float* c, const unsigned* a, const unsigned* b) {
    asm volatile(
        "mma.sync.aligned.m16n8k8.row.col.f32.tf32.tf32.f32 "
        "{%0,%1,%2,%3}, {%4,%5,%6,%7}, {%8,%9}, {%0,%1,%2,%3};"
        : "+f"(c[0]), "+f"(c[1]), "+f"(c[2]), "+f"(c[3])
        : "r"(a[0]), "r"(a[1]), "r"(a[2]), "r"(a[3]), "r"(b[0]), "r"(b[1]));
}

// ---------------------------------------------------------------------------
// Prep: weight repacks (K-major, tf32-rounded) + x rounding
// ---------------------------------------------------------------------------
__global__ void prep_x(const float* __restrict__ x) {
    int i = blockIdx.x * 256 + threadIdx.x;
    float4 v = ((const float4*)x)[i];
    v.x = f2tf_f(v.x); v.y = f2tf_f(v.y); v.z = f2tf_f(v.z); v.w = f2tf_f(v.w);
    ((float4*)g_Xc)[i] = v;
}
__global__ void prep_w1(const float* __restrict__ W1) {      // [512,2048] -> [2048,512]
    int i = blockIdx.x * 256 + threadIdx.x;
    int n = i >> 9, d = i & 511;
    g_W1t[i] = f2tf_f(W1[d * FF + n]);
}
__global__ void prep_w2(const float* __restrict__ W2) {      // [2048,512] -> [512,2048]
    int i = blockIdx.x * 256 + threadIdx.x;
    int d = i >> 11, f = i & 2047;
    g_W2t[i] = f2tf_f(W2[f * DD + d]);
}
__global__ void prep_wa(const float* __restrict__ Wa1, const float* __restrict__ Wa2) {
    int i = blockIdx.x * 256 + threadIdx.x;                  // -> [1024,512]
    int n = i >> 9, d = i & 511;
    int L = n >> 9, c = n & 511;
    const float* Wa = L ? Wa2 : Wa1;                         // [E,D,H]
    g_WaTt[i] = f2tf_f(Wa[((c >> 6) * DD + d) * 64 + (c & 63)]);
}
__global__ void prep_wb(const float* __restrict__ Wb1, const float* __restrict__ Wb2) {
    int i = blockIdx.x * 256 + threadIdx.x;                  // -> [512,1024]
    int d = i >> 10, j = i & 1023;
    const float* Wb = (j >> 9) ? Wb2 : Wb1;                  // [E,H,D] flat [512,512]
    g_Wbt[i] = f2tf_f(Wb[(j & 511) * DD + d]);
}

// ---------------------------------------------------------------------------
// Gating: one warp per token (on raw fp32 x — routing bit-exact)
// ---------------------------------------------------------------------------
__device__ __forceinline__ void write_top2(const float* a, float* o) {
    int i0 = 0; float v0 = a[0];
#pragma unroll
    for (int e = 1; e < 8; e++) if (a[e] > v0) { v0 = a[e]; i0 = e; }
    int i1 = -1; float v1 = -3.4e38f;
#pragma unroll
    for (int e = 0; e < 8; e++) if (e != i0 && a[e] > v1) { v1 = a[e]; i1 = e; }
    float t = expf(v1 - v0);
    float inv = 1.0f / (1.0f + t);
#pragma unroll
    for (int e = 0; e < 8; e++) o[e] = 0.0f;
    o[i0] = inv;
    o[i1] = t * inv;
}

__global__ void gate_kernel(const float* __restrict__ x,
                            const float* __restrict__ Wg1,
                            const float* __restrict__ Wg2) {
    int tok = blockIdx.x * 8 + (threadIdx.x >> 5);
    int lane = threadIdx.x & 31;
    if (tok >= TT) return;
    const float* xr = x + (size_t)tok * DD;
    float a1[8], a2[8];
#pragma unroll
    for (int e = 0; e < 8; e++) { a1[e] = 0.0f; a2[e] = 0.0f; }
    for (int j = lane; j < DD; j += 32) {
        float xv = xr[j];
#pragma unroll
        for (int e = 0; e < 8; e++) {
            a1[e] = fmaf(xv, Wg1[j * 8 + e], a1[e]);
            a2[e] = fmaf(xv, Wg2[j * 8 + e], a2[e]);
        }
    }
#pragma unroll
    for (int e = 0; e < 8; e++) {
#pragma unroll
        for (int o = 16; o; o >>= 1) {
            a1[e] += __shfl_xor_sync(0xffffffffu, a1[e], o);
            a2[e] += __shfl_xor_sync(0xffffffffu, a2[e], o);
        }
    }
    if (lane == 0) {
        write_top2(a1, &g_w[tok * 16]);
        write_top2(a2, &g_w[tok * 16 + 8]);
    }
}

// ---------------------------------------------------------------------------
// tf32 mma.sync GEMM: 128x128 tile, BK=32, 3-stage cp.async, 256 threads,
// 2 CTAs/SM. Operands pre-rounded to tf32 — mainloop is pure ldmatrix+mma.
// 8 warps in a 2x4 grid; each warp computes 64x32.
// EPI 0: H1 = tf32(gelu(acc + bias))     EPI 1: out = acc + bias
// EPI 2: Hm = tf32(mask * w * gelu(acc)) EPI 3: out += acc (rows s>=id)
// ---------------------------------------------------------------------------
template <int EPI>
__global__ __launch_bounds__(256, 2)
void gemm_mma(const float* __restrict__ A, const float* __restrict__ Bt,
              const float* __restrict__ bias, float* __restrict__ C,
              int K, int ldc, const int* __restrict__ idp)
{
    const int col0 = blockIdx.x * BN;
    const int row0 = blockIdx.y * BM;
    int idv = 0;
    if (EPI >= 2) {
        idv = *idp;
        if ((row0 & (SS - 1)) + BM - 1 < idv) return;   // tile fully masked
    }

    extern __shared__ float sm[];
    const unsigned smb = (unsigned)__cvta_generic_to_shared(sm);
    const int tid  = threadIdx.x;
    const int wid  = tid >> 5;
    const int lane = tid & 31;
    const int KT   = K >> 5;

    const int m0 = (wid >> 2) * 64;     // warp row offset in tile
    const int n0 = (wid & 3) * 32;      // warp col offset in tile

    const unsigned aoff = ((m0 + (lane & 7) + ((lane >> 3) & 1) * 8) * PADW
                           + (lane >> 4) * 4) * 4;
    const unsigned boff = ((BM + n0 + (lane & 7) + ((lane >> 3) & 2) * 4) * PADW
                           + ((lane >> 3) & 1) * 4) * 4;

    float acc[4][4][4];
#pragma unroll
    for (int i = 0; i < 4; i++)
#pragma unroll
        for (int j = 0; j < 4; j++)
#pragma unroll
            for (int r = 0; r < 4; r++) acc[i][j][r] = 0.0f;

    auto load_stage = [&](int st, int k0) {
        unsigned base = smb + (unsigned)(st * STG_FLOATS * 4);
#pragma unroll
        for (int i = 0; i < 8; i++) {
            int cid = tid + i * 256;
            int row = cid >> 3, c = cid & 7;
            unsigned dst = base + (unsigned)(row * PADW + c * 4) * 4;
            const float* src = (row < BM)
                ? A  + (size_t)(row0 + row) * K + k0 + c * 4
                : Bt + (size_t)(col0 + row - BM) * K + k0 + c * 4;
            cp16(dst, src);
        }
        asm volatile("cp.async.commit_group;" ::: "memory");
    };

    load_stage(0, 0);
    if (KT > 1) load_stage(1, BK);

#pragma unroll 1
    for (int kt = 0; kt < KT; kt++) {
        if (kt + 2 < KT) {
            load_stage((kt + 2) % NSTG, (kt + 2) * BK);
            asm volatile("cp.async.wait_group 2;" ::: "memory");
        } else if (kt + 1 < KT) {
            asm volatile("cp.async.wait_group 1;" ::: "memory");
        } else {
            asm volatile("cp.async.wait_group 0;" ::: "memory");
        }
        __syncthreads();

        const unsigned sbase = smb + (unsigned)((kt % NSTG) * STG_FLOATS * 4);
#pragma unroll
        for (int ks = 0; ks < 4; ks++) {
            const unsigned koff = ks * 32;     // 8 tf32 = 32B
            unsigned a[4][4];
#pragma unroll
            for (int mt = 0; mt < 4; mt++)
                ldsm4(a[mt][0], a[mt][1], a[mt][2], a[mt][3],
                      sbase + aoff + (unsigned)(mt * 16 * PADW * 4) + koff);
            unsigned b[4][2];
#pragma unroll
            for (int np = 0; np < 2; np++) {
                unsigned r0, r1, r2, r3;
                ldsm4(r0, r1, r2, r3,
                      sbase + boff + (unsigned)(np * 16 * PADW * 4) + koff);
                b[2*np][0]   = r0; b[2*np][1]   = r1;
                b[2*np+1][0] = r2; b[2*np+1][1] = r3;
            }
#pragma unroll
            for (int mt = 0; mt < 4; mt++)
#pragma unroll
                for (int nt = 0; nt < 4; nt++)
                    mma_tf32(acc[mt][nt], a[mt], b[nt]);
        }
        __syncthreads();
    }

    // ---- epilogue ----
    const int g = lane >> 2, t = lane & 3;
#pragma unroll
    for (int mt = 0; mt < 4; mt++) {
#pragma unroll
        for (int nt = 0; nt < 4; nt++) {
            int r0 = row0 + m0 + mt * 16 + g;
            int r1 = r0 + 8;
            int c  = col0 + n0 + nt * 8 + 2 * t;
            float* p0 = C + (size_t)r0 * ldc + c;
            float* p1 = C + (size_t)r1 * ldc + c;
            float v00 = acc[mt][nt][0], v01 = acc[mt][nt][1];
            float v10 = acc[mt][nt][2], v11 = acc[mt][nt][3];
            if (EPI == 0) {
                float2 bb = *(const float2*)(bias + c);
                float2 o0 = { f2tf_f(gelu_f(v00 + bb.x)), f2tf_f(gelu_f(v01 + bb.y)) };
                float2 o1 = { f2tf_f(gelu_f(v10 + bb.x)), f2tf_f(gelu_f(v11 + bb.y)) };
                *(float2*)p0 = o0; *(float2*)p1 = o1;
            } else if (EPI == 1) {
                float2 bb = *(const float2*)(bias + c);
                float2 o0 = { v00 + bb.x, v01 + bb.y };
                float2 o1 = { v10 + bb.x, v11 + bb.y };
                *(float2*)p0 = o0; *(float2*)p1 = o1;
            } else if (EPI == 2) {
                bool a0 = ((r0 & (SS - 1)) >= idv);
                bool a1 = ((r1 & (SS - 1)) >= idv);
                float w0 = a0 ? g_w[r0 * 16 + (c >> 6)] : 0.0f;
                float w1 = a1 ? g_w[r1 * 16 + (c >> 6)] : 0.0f;
                float2 o0 = { a0 ? f2tf_f(gelu_f(v00) * w0) : 0.0f,
                              a0 ? f2tf_f(gelu_f(v01) * w0) : 0.0f };
                float2 o1 = { a1 ? f2tf_f(gelu_f(v10) * w1) : 0.0f,
                              a1 ? f2tf_f(gelu_f(v11) * w1) : 0.0f };
                *(float2*)p0 = o0; *(float2*)p1 = o1;
            } else {  // EPI == 3
                if ((r0 & (SS - 1)) >= idv) {
                    float2 o = *(const float2*)p0;
                    o.x += v00; o.y += v01;
                    *(float2*)p0 = o;
                }
                if ((r1 & (SS - 1)) >= idv) {
                    float2 o = *(const float2*)p1;
                    o.x += v10; o.y += v11;
                    *(float2*)p1 = o;
                }
            }
        }
    }
}

// ---------------------------------------------------------------------------
extern "C" void kernel_launch(void* const* d_in, const int* in_sizes, int n_in,
                              void* d_out, int out_size) {
    const float* x   = (const float*)d_in[0];
    const int*   idp = (const int*)  d_in[1];
    const float* W1  = (const float*)d_in[2];
    const float* b1  = (const float*)d_in[3];
    const float* W2  = (const float*)d_in[4];
    const float* b2  = (const float*)d_in[5];
    const float* Wg1 = (const float*)d_in[6];
    const float* Wa1 = (const float*)d_in[7];
    const float* Wb1 = (const float*)d_in[8];
    const float* Wg2 = (const float*)d_in[9];
    const float* Wa2 = (const float*)d_in[10];
    const float* Wb2 = (const float*)d_in[11];
    float* out = (float*)d_out;
    (void)in_sizes; (void)n_in; (void)out_size;

    float *H1, *Hm, *Xc, *W1t, *W2t, *WaTt, *Wbt;
    cudaGetSymbolAddress((void**)&H1,   g_H1);
    cudaGetSymbolAddress((void**)&Hm,   g_Hm);
    cudaGetSymbolAddress((void**)&Xc,   g_Xc);
    cudaGetSymbolAddress((void**)&W1t,  g_W1t);
    cudaGetSymbolAddress((void**)&W2t,  g_W2t);
    cudaGetSymbolAddress((void**)&WaTt, g_WaTt);
    cudaGetSymbolAddress((void**)&Wbt,  g_Wbt);

    cudaFuncSetAttribute(gemm_mma<0>, cudaFuncAttributeMaxDynamicSharedMemorySize, SMEM_BYTES);
    cudaFuncSetAttribute(gemm_mma<1>, cudaFuncAttributeMaxDynamicSharedMemorySize, SMEM_BYTES);
    cudaFuncSetAttribute(gemm_mma<2>, cudaFuncAttributeMaxDynamicSharedMemorySize, SMEM_BYTES);
    cudaFuncSetAttribute(gemm_mma<3>, cudaFuncAttributeMaxDynamicSharedMemorySize, SMEM_BYTES);

    // Prep: operand rounding + repack + gating
    prep_x <<<(TT * (DD / 4)) / 256, 256>>>(x);
    prep_w1<<<FF * DD / 256, 256>>>(W1);
    prep_w2<<<DD * FF / 256, 256>>>(W2);
    prep_wa<<<NM * DD / 256, 256>>>(Wa1, Wa2);
    prep_wb<<<DD * NM / 256, 256>>>(Wb1, Wb2);
    gate_kernel<<<TT / 8, 256>>>(x, Wg1, Wg2);

    // FFN: out = gelu(x@W1 + b1) @ W2 + b2
    gemm_mma<0><<<dim3(FF / BN, TT / BM), 256, SMEM_BYTES>>>(Xc, W1t, b1, H1,  DD, FF, nullptr);
    gemm_mma<1><<<dim3(DD / BN, TT / BM), 256, SMEM_BYTES>>>(H1, W2t, b2, out, FF, DD, nullptr);

    // MoE (both layers fused): only tokens with s >= id do real work
    gemm_mma<2><<<dim3(NM / BN, TT / BM), 256, SMEM_BYTES>>>(Xc, WaTt, nullptr, Hm,  DD, NM, idp);
    gemm_mma<3><<<dim3(DD / BN, TT / BM), 256, SMEM_BYTES>>>(Hm, Wbt,  nullptr, out, NM, DD, idp);
}

// round 7
// speedup vs baseline: 1.4523x; 1.2977x over previous
#include <cuda_runtime.h>
#include <cuda_fp16.h>

#define TT 32768      // B*S tokens
#define SS 8192       // sequence length
#define DD 512        // model dim
#define FF 2048       // ffn hidden
#define NM 1024       // concatenated MoE hidden (2 layers * E*H)

#define BM 128
#define BN 128
#define BK 32                              // halves per K-chunk
#define NSTG 3
#define PADH 40                            // halves per smem row (80B)
#define STG_HALVES ((BM + BN) * PADH)      // 10240
#define STG_BYTES  (STG_HALVES * 2)        // 20480
#define SMEM_BYTES (NSTG * STG_BYTES)      // 61440

// Scratch (device globals; no allocation allowed)
__device__ __half g_H1[(unsigned long long)TT * FF];
__device__ __half g_Hm[(unsigned long long)TT * NM];
__device__ __half g_Xc[(unsigned long long)TT * DD];  // fp16 x
__device__ __half g_W1t[FF * DD];    // W1^T  [2048,512] K-major
__device__ __half g_W2t[DD * FF];    // W2^T  [512,2048] K-major
__device__ __half g_WaTt[NM * DD];   // MoE up weights [1024,512] K-major
__device__ __half g_Wbt[DD * NM];    // MoE down weights [512,1024] K-major
__device__ float  g_w[TT * 16];      // dense gate weights

__device__ __forceinline__ float gelu_f(float x) {
    float x3 = x * x * x;
    float t = tanhf(0.7978845608028654f * (x + 0.044715f * x3));
    return 0.5f * x * (1.0f + t);
}
__device__ __forceinline__ void cp16(unsigned dst, const void* src) {
    asm volatile("cp.async.cg.shared.global [%0], [%1], 16;" :: "r"(dst), "l"(src) : "memory");
}
__device__ __forceinline__ void ldsm4(unsigned& r0, unsigned& r1, unsigned& r2, unsigned& r3,
                                      unsigned addr) {
    asm volatile("ldmatrix.sync.aligned.m8n8.x4.shared.b16 {%0,%1,%2,%3}, [%4];"
                 : "=r"(r0), "=r"(r1), "=r"(r2), "=r"(r3) : "r"(addr));
}
__device__ __forceinline__ void mma_f16(float* c, const unsigned* a, const unsigned* b) {
    asm volatile(
        "mma.sync.aligned.m16n8k16.row.col.f32.f16.f16.f32 "
        "{%0,%1,%2,%3}, {%4,%5,%6,%7}, {%8,%9}, {%0,%1,%2,%3};"
        : "+f"(c[0]), "+f"(c[1]), "+f"(c[2]), "+f"(c[3])
        : "r"(a[0]), "r"(a[1]), "r"(a[2]), "r"(a[3]), "r"(b[0]), "r"(b[1]));
}

// ---------------------------------------------------------------------------
// Prep: weight repacks (K-major, fp16) + x conversion
// ---------------------------------------------------------------------------
__global__ void prep_x(const float* __restrict__ x) {
    int i = blockIdx.x * 256 + threadIdx.x;
    float4 v = ((const float4*)x)[i];
    __half2 h0 = { __float2half_rn(v.x), __float2half_rn(v.y) };
    __half2 h1 = { __float2half_rn(v.z), __float2half_rn(v.w) };
    ((__half2*)g_Xc)[i * 2]     = h0;
    ((__half2*)g_Xc)[i * 2 + 1] = h1;
}
__global__ void prep_w1(const float* __restrict__ W1) {      // [512,2048] -> [2048,512]
    int i = blockIdx.x * 256 + threadIdx.x;
    int n = i >> 9, d = i & 511;
    g_W1t[i] = __float2half_rn(W1[d * FF + n]);
}
__global__ void prep_w2(const float* __restrict__ W2) {      // [2048,512] -> [512,2048]
    int i = blockIdx.x * 256 + threadIdx.x;
    int d = i >> 11, f = i & 2047;
    g_W2t[i] = __float2half_rn(W2[f * DD + d]);
}
__global__ void prep_wa(const float* __restrict__ Wa1, const float* __restrict__ Wa2) {
    int i = blockIdx.x * 256 + threadIdx.x;                  // -> [1024,512]
    int n = i >> 9, d = i & 511;
    int L = n >> 9, c = n & 511;
    const float* Wa = L ? Wa2 : Wa1;                         // [E,D,H]
    g_WaTt[i] = __float2half_rn(Wa[((c >> 6) * DD + d) * 64 + (c & 63)]);
}
__global__ void prep_wb(const float* __restrict__ Wb1, const float* __restrict__ Wb2) {
    int i = blockIdx.x * 256 + threadIdx.x;                  // -> [512,1024]
    int d = i >> 10, j = i & 1023;
    const float* Wb = (j >> 9) ? Wb2 : Wb1;                  // [E,H,D] flat [512,512]
    g_Wbt[i] = __float2half_rn(Wb[(j & 511) * DD + d]);
}

// ---------------------------------------------------------------------------
// Gating: one warp per token (raw fp32 x — routing bit-exact)
// ---------------------------------------------------------------------------
__device__ __forceinline__ void write_top2(const float* a, float* o) {
    int i0 = 0; float v0 = a[0];
#pragma unroll
    for (int e = 1; e < 8; e++) if (a[e] > v0) { v0 = a[e]; i0 = e; }
    int i1 = -1; float v1 = -3.4e38f;
#pragma unroll
    for (int e = 0; e < 8; e++) if (e != i0 && a[e] > v1) { v1 = a[e]; i1 = e; }
    float t = expf(v1 - v0);
    float inv = 1.0f / (1.0f + t);
#pragma unroll
    for (int e = 0; e < 8; e++) o[e] = 0.0f;
    o[i0] = inv;
    o[i1] = t * inv;
}

__global__ void gate_kernel(const float* __restrict__ x,
                            const float* __restrict__ Wg1,
                            const float* __restrict__ Wg2) {
    int tok = blockIdx.x * 8 + (threadIdx.x >> 5);
    int lane = threadIdx.x & 31;
    if (tok >= TT) return;
    const float* xr = x + (size_t)tok * DD;
    float a1[8], a2[8];
#pragma unroll
    for (int e = 0; e < 8; e++) { a1[e] = 0.0f; a2[e] = 0.0f; }
    for (int j = lane; j < DD; j += 32) {
        float xv = xr[j];
#pragma unroll
        for (int e = 0; e < 8; e++) {
            a1[e] = fmaf(xv, Wg1[j * 8 + e], a1[e]);
            a2[e] = fmaf(xv, Wg2[j * 8 + e], a2[e]);
        }
    }
#pragma unroll
    for (int e = 0; e < 8; e++) {
#pragma unroll
        for (int o = 16; o; o >>= 1) {
            a1[e] += __shfl_xor_sync(0xffffffffu, a1[e], o);
            a2[e] += __shfl_xor_sync(0xffffffffu, a2[e], o);
        }
    }
    if (lane == 0) {
        write_top2(a1, &g_w[tok * 16]);
        write_top2(a2, &g_w[tok * 16 + 8]);
    }
}

// ---------------------------------------------------------------------------
// fp16 mma.sync GEMM: 128x128 tile, BK=32, 3-stage cp.async, 256 threads,
// 2 CTAs/SM. 8 warps in a 2x4 grid; each warp computes 64x32 via m16n8k16.
// A [M,K] K-major fp16, Bt [N,K] K-major fp16.
// EPI 0: H1(fp16) = gelu(acc + bias)     EPI 1: out(fp32) = acc + bias
// EPI 2: Hm(fp16) = mask * w * gelu(acc) EPI 3: out(fp32) += acc (rows s>=id)
// ---------------------------------------------------------------------------
template <int EPI>
__global__ __launch_bounds__(256, 2)
void gemm_mma(const __half* __restrict__ A, const __half* __restrict__ Bt,
              const float* __restrict__ bias, void* __restrict__ Cv,
              int K, int ldc, const int* __restrict__ idp)
{
    const int col0 = blockIdx.x * BN;
    const int row0 = blockIdx.y * BM;
    int idv = 0;
    if (EPI >= 2) {
        idv = *idp;
        if ((row0 & (SS - 1)) + BM - 1 < idv) return;   // tile fully masked
    }

    extern __shared__ __half sm[];
    const unsigned smb = (unsigned)__cvta_generic_to_shared(sm);
    const int tid  = threadIdx.x;
    const int wid  = tid >> 5;
    const int lane = tid & 31;
    const int KT   = K >> 5;

    const int m0 = (wid >> 2) * 64;     // warp row offset in tile
    const int n0 = (wid & 3) * 32;      // warp col offset in tile

    // ldmatrix per-lane byte offsets within a stage (row = lane&15, col-16B = lane>>4)
    const unsigned aoff = (unsigned)((m0 + (lane & 15)) * (PADH * 2) + (lane >> 4) * 16);
    const unsigned boff = (unsigned)((BM + n0 + (lane & 15)) * (PADH * 2) + (lane >> 4) * 16);

    float acc[4][4][4];
#pragma unroll
    for (int i = 0; i < 4; i++)
#pragma unroll
        for (int j = 0; j < 4; j++)
#pragma unroll
            for (int r = 0; r < 4; r++) acc[i][j][r] = 0.0f;

    auto load_stage = [&](int st, int k0) {
        unsigned base = smb + (unsigned)(st * STG_BYTES);
#pragma unroll
        for (int i = 0; i < 4; i++) {
            int cid = tid + i * 256;            // 0..1023
            int row = cid >> 2, c = cid & 3;    // 4 x 16B per 64B row
            unsigned dst = base + (unsigned)(row * (PADH * 2) + c * 16);
            const __half* src = (row < BM)
                ? A  + (size_t)(row0 + row) * K + k0 + c * 8
                : Bt + (size_t)(col0 + row - BM) * K + k0 + c * 8;
            cp16(dst, src);
        }
        asm volatile("cp.async.commit_group;" ::: "memory");
    };

    load_stage(0, 0);
    if (KT > 1) load_stage(1, BK);

#pragma unroll 1
    for (int kt = 0; kt < KT; kt++) {
        if (kt + 2 < KT) {
            load_stage((kt + 2) % NSTG, (kt + 2) * BK);
            asm volatile("cp.async.wait_group 2;" ::: "memory");
        } else if (kt + 1 < KT) {
            asm volatile("cp.async.wait_group 1;" ::: "memory");
        } else {
            asm volatile("cp.async.wait_group 0;" ::: "memory");
        }
        __syncthreads();

        const unsigned sbase = smb + (unsigned)((kt % NSTG) * STG_BYTES);
#pragma unroll
        for (int ks = 0; ks < 2; ks++) {
            const unsigned koff = ks * 32;     // 16 halves = 32B
            unsigned a[4][4];
#pragma unroll
            for (int mt = 0; mt < 4; mt++)
                ldsm4(a[mt][0], a[mt][1], a[mt][2], a[mt][3],
                      sbase + aoff + (unsigned)(mt * 16 * PADH * 2) + koff);
            unsigned b[4][2];
#pragma unroll
            for (int np = 0; np < 2; np++) {
                unsigned r0, r1, r2, r3;
                ldsm4(r0, r1, r2, r3,
                      sbase + boff + (unsigned)(np * 16 * PADH * 2) + koff);
                b[2*np][0]   = r0; b[2*np][1]   = r2;   // n 0-7:  {k0-7, k8-15}
                b[2*np+1][0] = r1; b[2*np+1][1] = r3;   // n 8-15: {k0-7, k8-15}
            }
#pragma unroll
            for (int mt = 0; mt < 4; mt++)
#pragma unroll
                for (int nt = 0; nt < 4; nt++)
                    mma_f16(acc[mt][nt], a[mt], b[nt]);
        }
        __syncthreads();
    }

    // ---- epilogue ----
    const int g = lane >> 2, t = lane & 3;
#pragma unroll
    for (int mt = 0; mt < 4; mt++) {
#pragma unroll
        for (int nt = 0; nt < 4; nt++) {
            int r0 = row0 + m0 + mt * 16 + g;
            int r1 = r0 + 8;
            int c  = col0 + n0 + nt * 8 + 2 * t;
            float v00 = acc[mt][nt][0], v01 = acc[mt][nt][1];
            float v10 = acc[mt][nt][2], v11 = acc[mt][nt][3];
            if (EPI == 0) {
                __half* Ch = (__half*)Cv;
                float2 bb = *(const float2*)(bias + c);
                __half2 o0 = { __float2half_rn(gelu_f(v00 + bb.x)),
                               __float2half_rn(gelu_f(v01 + bb.y)) };
                __half2 o1 = { __float2half_rn(gelu_f(v10 + bb.x)),
                               __float2half_rn(gelu_f(v11 + bb.y)) };
                *(__half2*)(Ch + (size_t)r0 * ldc + c) = o0;
                *(__half2*)(Ch + (size_t)r1 * ldc + c) = o1;
            } else if (EPI == 1) {
                float* Cf = (float*)Cv;
                float2 bb = *(const float2*)(bias + c);
                float2 o0 = { v00 + bb.x, v01 + bb.y };
                float2 o1 = { v10 + bb.x, v11 + bb.y };
                *(float2*)(Cf + (size_t)r0 * ldc + c) = o0;
                *(float2*)(Cf + (size_t)r1 * ldc + c) = o1;
            } else if (EPI == 2) {
                __half* Ch = (__half*)Cv;
                bool a0 = ((r0 & (SS - 1)) >= idv);
                bool a1 = ((r1 & (SS - 1)) >= idv);
                float w0 = a0 ? g_w[r0 * 16 + (c >> 6)] : 0.0f;
                float w1 = a1 ? g_w[r1 * 16 + (c >> 6)] : 0.0f;
                __half2 o0 = { __float2half_rn(a0 ? gelu_f(v00) * w0 : 0.0f),
                               __float2half_rn(a0 ? gelu_f(v01) * w0 : 0.0f) };
                __half2 o1 = { __float2half_rn(a1 ? gelu_f(v10) * w1 : 0.0f),
                               __float2half_rn(a1 ? gelu_f(v11) * w1 : 0.0f) };
                *(__half2*)(Ch + (size_t)r0 * ldc + c) = o0;
                *(__half2*)(Ch + (size_t)r1 * ldc + c) = o1;
            } else {  // EPI == 3
                float* Cf = (float*)Cv;
                if ((r0 & (SS - 1)) >= idv) {
                    float2 o = *(const float2*)(Cf + (size_t)r0 * ldc + c);
                    o.x += v00; o.y += v01;
                    *(float2*)(Cf + (size_t)r0 * ldc + c) = o;
                }
                if ((r1 & (SS - 1)) >= idv) {
                    float2 o = *(const float2*)(Cf + (size_t)r1 * ldc + c);
                    o.x += v10; o.y += v11;
                    *(float2*)(Cf + (size_t)r1 * ldc + c) = o;
                }
            }
        }
    }
}

// ---------------------------------------------------------------------------
extern "C" void kernel_launch(void* const* d_in, const int* in_sizes, int n_in,
                              void* d_out, int out_size) {
    const float* x   = (const float*)d_in[0];
    const int*   idp = (const int*)  d_in[1];
    const float* W1  = (const float*)d_in[2];
    const float* b1  = (const float*)d_in[3];
    const float* W2  = (const float*)d_in[4];
    const float* b2  = (const float*)d_in[5];
    const float* Wg1 = (const float*)d_in[6];
    const float* Wa1 = (const float*)d_in[7];
    const float* Wb1 = (const float*)d_in[8];
    const float* Wg2 = (const float*)d_in[9];
    const float* Wa2 = (const float*)d_in[10];
    const float* Wb2 = (const float*)d_in[11];
    float* out = (float*)d_out;
    (void)in_sizes; (void)n_in; (void)out_size;

    __half *H1, *Hm, *Xc, *W1t, *W2t, *WaTt, *Wbt;
    cudaGetSymbolAddress((void**)&H1,   g_H1);
    cudaGetSymbolAddress((void**)&Hm,   g_Hm);
    cudaGetSymbolAddress((void**)&Xc,   g_Xc);
    cudaGetSymbolAddress((void**)&W1t,  g_W1t);
    cudaGetSymbolAddress((void**)&W2t,  g_W2t);
    cudaGetSymbolAddress((void**)&WaTt, g_WaTt);
    cudaGetSymbolAddress((void**)&Wbt,  g_Wbt);

    cudaFuncSetAttribute(gemm_mma<0>, cudaFuncAttributeMaxDynamicSharedMemorySize, SMEM_BYTES);
    cudaFuncSetAttribute(gemm_mma<1>, cudaFuncAttributeMaxDynamicSharedMemorySize, SMEM_BYTES);
    cudaFuncSetAttribute(gemm_mma<2>, cudaFuncAttributeMaxDynamicSharedMemorySize, SMEM_BYTES);
    cudaFuncSetAttribute(gemm_mma<3>, cudaFuncAttributeMaxDynamicSharedMemorySize, SMEM_BYTES);

    // Prep: fp16 conversion + repack + gating
    prep_x <<<(TT * (DD / 4)) / 256, 256>>>(x);
    prep_w1<<<FF * DD / 256, 256>>>(W1);
    prep_w2<<<DD * FF / 256, 256>>>(W2);
    prep_wa<<<NM * DD / 256, 256>>>(Wa1, Wa2);
    prep_wb<<<DD * NM / 256, 256>>>(Wb1, Wb2);
    gate_kernel<<<TT / 8, 256>>>(x, Wg1, Wg2);

    // FFN: out = gelu(x@W1 + b1) @ W2 + b2
    gemm_mma<0><<<dim3(FF / BN, TT / BM), 256, SMEM_BYTES>>>(Xc, W1t, b1, H1,  DD, FF, nullptr);
    gemm_mma<1><<<dim3(DD / BN, TT / BM), 256, SMEM_BYTES>>>(H1, W2t, b2, out, FF, DD, nullptr);

    // MoE (both layers fused): only tokens with s >= id do real work
    gemm_mma<2><<<dim3(NM / BN, TT / BM), 256, SMEM_BYTES>>>(Xc, WaTt, nullptr, Hm,  DD, NM, idp);
    gemm_mma<3><<<dim3(DD / BN, TT / BM), 256, SMEM_BYTES>>>(Hm, Wbt,  nullptr, out, NM, DD, idp);
}

// round 8
// speedup vs baseline: 1.7633x; 1.2141x over previous
#include <cuda_runtime.h>
#include <cuda_fp16.h>

#define TT 32768      // B*S tokens
#define SS 8192       // sequence length
#define DD 512        // model dim
#define FF 2048       // ffn hidden
#define NMOE 1024     // concatenated MoE hidden (2 layers * E*H)
#define NUP (FF + NMOE)   // 3072 fused up-projection width

#define BM 128
#define BN 128
#define BK 64                              // halves per K-chunk (128B rows)
#define NSTG 3
#define ROWB 128                           // bytes per smem row
#define STG_BYTES ((BM + BN) * ROWB)       // 32768
#define SMEM_BYTES (NSTG * STG_BYTES)      // 98304

// Scratch (device globals; no allocation allowed)
__device__ __half g_H[(unsigned long long)TT * NUP];   // [H1 | Hm] fused hidden, 192MB
__device__ __half g_Xc[(unsigned long long)TT * DD];   // fp16 x
__device__ __half g_Wu[NUP * DD];    // stacked up weights   [3072,512] K-major
__device__ __half g_Wd[DD * NUP];    // stacked down weights [512,3072] K-major
__device__ float  g_w[TT * 16];      // dense gate weights

__device__ __forceinline__ float gelu_f(float x) {
    float x3 = x * x * x;
    float t = tanhf(0.7978845608028654f * (x + 0.044715f * x3));
    return 0.5f * x * (1.0f + t);
}
__device__ __forceinline__ void cp16(unsigned dst, const void* src) {
    asm volatile("cp.async.cg.shared.global [%0], [%1], 16;" :: "r"(dst), "l"(src) : "memory");
}
__device__ __forceinline__ void ldsm4(unsigned& r0, unsigned& r1, unsigned& r2, unsigned& r3,
                                      unsigned addr) {
    asm volatile("ldmatrix.sync.aligned.m8n8.x4.shared.b16 {%0,%1,%2,%3}, [%4];"
                 : "=r"(r0), "=r"(r1), "=r"(r2), "=r"(r3) : "r"(addr));
}
__device__ __forceinline__ void mma_f16(float* c, const unsigned* a, const unsigned* b) {
    asm volatile(
        "mma.sync.aligned.m16n8k16.row.col.f32.f16.f16.f32 "
        "{%0,%1,%2,%3}, {%4,%5,%6,%7}, {%8,%9}, {%0,%1,%2,%3};"
        : "+f"(c[0]), "+f"(c[1]), "+f"(c[2]), "+f"(c[3])
        : "r"(a[0]), "r"(a[1]), "r"(a[2]), "r"(a[3]), "r"(b[0]), "r"(b[1]));
}

// ---------------------------------------------------------------------------
// Prep: stacked weight repacks (K-major fp16) + x conversion
// ---------------------------------------------------------------------------
__global__ void prep_x(const float* __restrict__ x) {
    int i = blockIdx.x * 256 + threadIdx.x;
    float4 v = ((const float4*)x)[i];
    __half2 h0 = { __float2half_rn(v.x), __float2half_rn(v.y) };
    __half2 h1 = { __float2half_rn(v.z), __float2half_rn(v.w) };
    ((__half2*)g_Xc)[i * 2]     = h0;
    ((__half2*)g_Xc)[i * 2 + 1] = h1;
}
// g_Wu[n*512+d]: n<2048 -> W1[d][n]; else MoE col c=n-2048 from Wa_L[e,d,h]
__global__ void prep_wu(const float* __restrict__ W1,
                        const float* __restrict__ Wa1, const float* __restrict__ Wa2) {
    int i = blockIdx.x * 256 + threadIdx.x;       // 0 .. 3072*512-1
    int n = i >> 9, d = i & 511;
    float v;
    if (n < FF) {
        v = W1[d * FF + n];
    } else {
        int c = n - FF;                            // 0..1023
        const float* Wa = (c >> 9) ? Wa2 : Wa1;    // [E,D,H]
        int cc = c & 511;
        v = Wa[((cc >> 6) * DD + d) * 64 + (cc & 63)];
    }
    g_Wu[i] = __float2half_rn(v);
}
// g_Wd[d*3072+k]: k<2048 -> W2[k][d]; else Wb_L[(k-2048)&511][d]
__global__ void prep_wd(const float* __restrict__ W2,
                        const float* __restrict__ Wb1, const float* __restrict__ Wb2) {
    int i = blockIdx.x * 256 + threadIdx.x;       // 0 .. 512*3072-1
    int d = i / NUP, k = i % NUP;
    float v;
    if (k < FF) {
        v = W2[k * DD + d];
    } else {
        int j = k - FF;                            // 0..1023
        const float* Wb = (j >> 9) ? Wb2 : Wb1;    // flat [512,512]
        v = Wb[(j & 511) * DD + d];
    }
    g_Wd[i] = __float2half_rn(v);
}

// ---------------------------------------------------------------------------
// Gating: one warp per token (raw fp32 x — routing bit-exact)
// ---------------------------------------------------------------------------
__device__ __forceinline__ void write_top2(const float* a, float* o) {
    int i0 = 0; float v0 = a[0];
#pragma unroll
    for (int e = 1; e < 8; e++) if (a[e] > v0) { v0 = a[e]; i0 = e; }
    int i1 = -1; float v1 = -3.4e38f;
#pragma unroll
    for (int e = 0; e < 8; e++) if (e != i0 && a[e] > v1) { v1 = a[e]; i1 = e; }
    float t = expf(v1 - v0);
    float inv = 1.0f / (1.0f + t);
#pragma unroll
    for (int e = 0; e < 8; e++) o[e] = 0.0f;
    o[i0] = inv;
    o[i1] = t * inv;
}

__global__ void gate_kernel(const float* __restrict__ x,
                            const float* __restrict__ Wg1,
                            const float* __restrict__ Wg2) {
    int tok = blockIdx.x * 8 + (threadIdx.x >> 5);
    int lane = threadIdx.x & 31;
    if (tok >= TT) return;
    const float* xr = x + (size_t)tok * DD;
    float a1[8], a2[8];
#pragma unroll
    for (int e = 0; e < 8; e++) { a1[e] = 0.0f; a2[e] = 0.0f; }
    for (int j = lane; j < DD; j += 32) {
        float xv = xr[j];
#pragma unroll
        for (int e = 0; e < 8; e++) {
            a1[e] = fmaf(xv, Wg1[j * 8 + e], a1[e]);
            a2[e] = fmaf(xv, Wg2[j * 8 + e], a2[e]);
        }
    }
#pragma unroll
    for (int e = 0; e < 8; e++) {
#pragma unroll
        for (int o = 16; o; o >>= 1) {
            a1[e] += __shfl_xor_sync(0xffffffffu, a1[e], o);
            a2[e] += __shfl_xor_sync(0xffffffffu, a2[e], o);
        }
    }
    if (lane == 0) {
        write_top2(a1, &g_w[tok * 16]);
        write_top2(a2, &g_w[tok * 16 + 8]);
    }
}

// ===========================================================================
// Shared GEMM machinery: 128x128 tile, BK=64, XOR-swizzled smem, 3-stage
// cp.async, 256 threads, 2 CTAs/SM. 8 warps (2x4); each warp 64x32.
// ===========================================================================

// Per-lane swizzled k-slot byte offset: slot = ks*2 + (lane>>4), XOR (lane&7)
#define KOFF(ks, lane) ((unsigned)((((ks) * 2 + ((lane) >> 4)) ^ ((lane) & 7)) << 4))

struct Frag { float acc[4][4][4]; };

template <typename LoadA>
__device__ __forceinline__ void gemm_core(
    Frag& F, unsigned smb, int tid, int lane, int m0, int n0, int KT,
    LoadA srcA, const __half* __restrict__ Bt, int ldb, int col0)
{
    auto load_stage = [&](int st, int k0) {
        unsigned base = smb + (unsigned)(st * STG_BYTES);
#pragma unroll
        for (int i = 0; i < 8; i++) {
            int cid = tid + i * 256;                 // 0..2047
            int row = cid >> 3, c = cid & 7;         // 8 x 16B per 128B row
            unsigned dst = base + (unsigned)(row * ROWB + ((c ^ (row & 7)) << 4));
            const __half* src = (row < BM)
                ? srcA(row, k0 + c * 8)
                : Bt + (size_t)(col0 + row - BM) * ldb + k0 + c * 8;
            cp16(dst, src);
        }
        asm volatile("cp.async.commit_group;" ::: "memory");
    };

    const unsigned arow = (unsigned)((m0 + (lane & 15)) * ROWB);
    const unsigned brow = (unsigned)((BM + n0 + (lane & 15)) * ROWB);

    load_stage(0, 0);
    load_stage(1, BK);

#pragma unroll 1
    for (int kt = 0; kt < KT; kt++) {
        if (kt + 2 < KT) {
            load_stage((kt + 2) % NSTG, (kt + 2) * BK);
            asm volatile("cp.async.wait_group 2;" ::: "memory");
        } else if (kt + 1 < KT) {
            asm volatile("cp.async.wait_group 1;" ::: "memory");
        } else {
            asm volatile("cp.async.wait_group 0;" ::: "memory");
        }
        __syncthreads();

        const unsigned sbase = smb + (unsigned)((kt % NSTG) * STG_BYTES);
#pragma unroll
        for (int ks = 0; ks < 4; ks++) {
            const unsigned koff = KOFF(ks, lane);
            unsigned a[4][4];
#pragma unroll
            for (int mt = 0; mt < 4; mt++)
                ldsm4(a[mt][0], a[mt][1], a[mt][2], a[mt][3],
                      sbase + arow + (unsigned)(mt * 16 * ROWB) + koff);
            unsigned b[4][2];
#pragma unroll
            for (int np = 0; np < 2; np++) {
                unsigned r0, r1, r2, r3;
                ldsm4(r0, r1, r2, r3,
                      sbase + brow + (unsigned)(np * 16 * ROWB) + koff);
                b[2*np][0]   = r0; b[2*np][1]   = r2;
                b[2*np+1][0] = r1; b[2*np+1][1] = r3;
            }
#pragma unroll
            for (int mt = 0; mt < 4; mt++)
#pragma unroll
                for (int nt = 0; nt < 4; nt++)
                    mma_f16(F.acc[mt][nt], a[mt], b[nt]);
        }
        __syncthreads();
    }
}

// ---------------------------------------------------------------------------
// Fused up-GEMM: g_H[:, :3072] = { gelu(x@W1+b1) | mask*w*gelu(x@Wa) }
// Grid (24, 256). Col tiles 0..15 = FFN, 16..23 = MoE (early-exit if masked).
// ---------------------------------------------------------------------------
__global__ __launch_bounds__(256, 2)
void gemm_up(const __half* __restrict__ A, const float* __restrict__ b1,
             const int* __restrict__ idp)
{
    const int col0 = blockIdx.x * BN;
    const int row0 = blockIdx.y * BM;
    const bool moe = (col0 >= FF);
    const int idv = *idp;
    if (moe && (row0 & (SS - 1)) + BM - 1 < idv) return;   // fully masked MoE tile

    extern __shared__ __half sm[];
    const unsigned smb = (unsigned)__cvta_generic_to_shared(sm);
    const int tid = threadIdx.x, wid = tid >> 5, lane = tid & 31;
    const int m0 = (wid >> 2) * 64, n0 = (wid & 3) * 32;

    Frag F;
#pragma unroll
    for (int i = 0; i < 4; i++)
#pragma unroll
        for (int j = 0; j < 4; j++)
#pragma unroll
            for (int r = 0; r < 4; r++) F.acc[i][j][r] = 0.0f;

    auto srcA = [&](int row, int k) { return A + (size_t)(row0 + row) * DD + k; };
    gemm_core(F, smb, tid, lane, m0, n0, DD / BK, srcA, g_Wu, DD, col0);

    const int g = lane >> 2, t = lane & 3;
#pragma unroll
    for (int mt = 0; mt < 4; mt++) {
#pragma unroll
        for (int nt = 0; nt < 4; nt++) {
            int r0 = row0 + m0 + mt * 16 + g;
            int r1 = r0 + 8;
            int c  = col0 + n0 + nt * 8 + 2 * t;
            float v00 = F.acc[mt][nt][0], v01 = F.acc[mt][nt][1];
            float v10 = F.acc[mt][nt][2], v11 = F.acc[mt][nt][3];
            __half2 o0, o1;
            if (!moe) {
                float2 bb = *(const float2*)(b1 + c);
                o0 = { __float2half_rn(gelu_f(v00 + bb.x)), __float2half_rn(gelu_f(v01 + bb.y)) };
                o1 = { __float2half_rn(gelu_f(v10 + bb.x)), __float2half_rn(gelu_f(v11 + bb.y)) };
            } else {
                bool a0 = ((r0 & (SS - 1)) >= idv);
                bool a1 = ((r1 & (SS - 1)) >= idv);
                int e = (c - FF) >> 6;                 // 0..15
                float w0 = a0 ? g_w[r0 * 16 + e] : 0.0f;
                float w1 = a1 ? g_w[r1 * 16 + e] : 0.0f;
                o0 = { __float2half_rn(a0 ? gelu_f(v00) * w0 : 0.0f),
                       __float2half_rn(a0 ? gelu_f(v01) * w0 : 0.0f) };
                o1 = { __float2half_rn(a1 ? gelu_f(v10) * w1 : 0.0f),
                       __float2half_rn(a1 ? gelu_f(v11) * w1 : 0.0f) };
            }
            *(__half2*)(g_H + (size_t)r0 * NUP + c) = o0;
            *(__half2*)(g_H + (size_t)r1 * NUP + c) = o1;
        }
    }
}

// ---------------------------------------------------------------------------
// Fused down-GEMM: out = g_H @ [W2t;Wbt]^T + b2.
// Fully-masked row tiles use K=2048 (skip MoE columns of g_H); others K=3072.
// Grid (4, 256).
// ---------------------------------------------------------------------------
__global__ __launch_bounds__(256, 2)
void gemm_down(const float* __restrict__ b2, float* __restrict__ out,
               const int* __restrict__ idp)
{
    const int col0 = blockIdx.x * BN;
    const int row0 = blockIdx.y * BM;
    const int idv = *idp;
    const bool fully_masked = ((row0 & (SS - 1)) + BM - 1 < idv);
    const int KT = (fully_masked ? FF : NUP) / BK;

    extern __shared__ __half sm[];
    const unsigned smb = (unsigned)__cvta_generic_to_shared(sm);
    const int tid = threadIdx.x, wid = tid >> 5, lane = tid & 31;
    const int m0 = (wid >> 2) * 64, n0 = (wid & 3) * 32;

    Frag F;
#pragma unroll
    for (int i = 0; i < 4; i++)
#pragma unroll
        for (int j = 0; j < 4; j++)
#pragma unroll
            for (int r = 0; r < 4; r++) F.acc[i][j][r] = 0.0f;

    auto srcA = [&](int row, int k) { return g_H + (size_t)(row0 + row) * NUP + k; };
    gemm_core(F, smb, tid, lane, m0, n0, KT, srcA, g_Wd, NUP, col0);

    const int g = lane >> 2, t = lane & 3;
#pragma unroll
    for (int mt = 0; mt < 4; mt++) {
#pragma unroll
        for (int nt = 0; nt < 4; nt++) {
            int r0 = row0 + m0 + mt * 16 + g;
            int r1 = r0 + 8;
            int c  = col0 + n0 + nt * 8 + 2 * t;
            float2 bb = *(const float2*)(b2 + c);
            float2 o0 = { F.acc[mt][nt][0] + bb.x, F.acc[mt][nt][1] + bb.y };
            float2 o1 = { F.acc[mt][nt][2] + bb.x, F.acc[mt][nt][3] + bb.y };
            *(float2*)(out + (size_t)r0 * DD + c) = o0;
            *(float2*)(out + (size_t)r1 * DD + c) = o1;
        }
    }
}

// ---------------------------------------------------------------------------
extern "C" void kernel_launch(void* const* d_in, const int* in_sizes, int n_in,
                              void* d_out, int out_size) {
    const float* x   = (const float*)d_in[0];
    const int*   idp = (const int*)  d_in[1];
    const float* W1  = (const float*)d_in[2];
    const float* b1  = (const float*)d_in[3];
    const float* W2  = (const float*)d_in[4];
    const float* b2  = (const float*)d_in[5];
    const float* Wg1 = (const float*)d_in[6];
    const float* Wa1 = (const float*)d_in[7];
    const float* Wb1 = (const float*)d_in[8];
    const float* Wg2 = (const float*)d_in[9];
    const float* Wa2 = (const float*)d_in[10];
    const float* Wb2 = (const float*)d_in[11];
    float* out = (float*)d_out;
    (void)in_sizes; (void)n_in; (void)out_size;

    __half* Xc;
    cudaGetSymbolAddress((void**)&Xc, g_Xc);

    cudaFuncSetAttribute(gemm_up,   cudaFuncAttributeMaxDynamicSharedMemorySize, SMEM_BYTES);
    cudaFuncSetAttribute(gemm_down, cudaFuncAttributeMaxDynamicSharedMemorySize, SMEM_BYTES);

    // Prep: fp16 conversion + stacked repacks + gating
    prep_x <<<(TT * (DD / 4)) / 256, 256>>>(x);
    prep_wu<<<NUP * DD / 256, 256>>>(W1, Wa1, Wa2);
    prep_wd<<<DD * NUP / 256, 256>>>(W2, Wb1, Wb2);
    gate_kernel<<<TT / 8, 256>>>(x, Wg1, Wg2);

    // Fused up-projection (FFN1 + both MoE up layers)
    gemm_up<<<dim3(NUP / BN, TT / BM), 256, SMEM_BYTES>>>(Xc, b1, idp);

    // Fused down-projection (FFN2 + both MoE down layers, single out write)
    gemm_down<<<dim3(DD / BN, TT / BM), 256, SMEM_BYTES>>>(b2, out, idp);
}

// round 9
// speedup vs baseline: 2.2456x; 1.2735x over previous
#include <cuda_runtime.h>
#include <cuda_fp16.h>

#define TT 32768      // B*S tokens
#define SS 8192       // sequence length
#define DD 512        // model dim
#define FF 2048       // ffn hidden
#define NMOE 1024     // concatenated MoE hidden (2 layers * E*H)
#define NUP (FF + NMOE)   // 3072 fused up-projection width

#define BM 128
#define BN 128
#define BK 64                              // halves per K-chunk (128B rows)
#define NSTG 3
#define ROWB 128                           // bytes per smem row
#define STG_BYTES ((BM + BN) * ROWB)       // 32768
#define SMEM_BYTES (NSTG * STG_BYTES)      // 98304

// Scratch (device globals; no allocation allowed)
__device__ __half g_H[(unsigned long long)TT * NUP];   // [H1 | Hm] fused hidden
__device__ __half g_Xc[(unsigned long long)TT * DD];   // fp16 x
__device__ __half g_Wu[NUP * DD];    // stacked up weights   [3072,512] K-major
__device__ __half g_Wd[DD * NUP];    // stacked down weights [512,3072] K-major
__device__ float  g_w[TT * 16];      // dense gate weights

__device__ __forceinline__ float gelu_f(float x) {
    float x3 = x * x * x;
    float t = tanhf(0.7978845608028654f * (x + 0.044715f * x3));
    return 0.5f * x * (1.0f + t);
}
__device__ __forceinline__ void cp16(unsigned dst, const void* src) {
    asm volatile("cp.async.cg.shared.global [%0], [%1], 16;" :: "r"(dst), "l"(src) : "memory");
}
__device__ __forceinline__ void ldsm4(unsigned& r0, unsigned& r1, unsigned& r2, unsigned& r3,
                                      unsigned addr) {
    asm volatile("ldmatrix.sync.aligned.m8n8.x4.shared.b16 {%0,%1,%2,%3}, [%4];"
                 : "=r"(r0), "=r"(r1), "=r"(r2), "=r"(r3) : "r"(addr));
}
__device__ __forceinline__ void mma_f16(float* c, const unsigned* a, const unsigned* b) {
    asm volatile(
        "mma.sync.aligned.m16n8k16.row.col.f32.f16.f16.f32 "
        "{%0,%1,%2,%3}, {%4,%5,%6,%7}, {%8,%9}, {%0,%1,%2,%3};"
        : "+f"(c[0]), "+f"(c[1]), "+f"(c[2]), "+f"(c[3])
        : "r"(a[0]), "r"(a[1]), "r"(a[2]), "r"(a[3]), "r"(b[0]), "r"(b[1]));
}

// ---------------------------------------------------------------------------
// Prep: stacked weight repacks (K-major fp16) + x conversion
// ---------------------------------------------------------------------------
__global__ void prep_x(const float* __restrict__ x) {
    int i = blockIdx.x * 256 + threadIdx.x;
    float4 v = ((const float4*)x)[i];
    __half2 h0 = { __float2half_rn(v.x), __float2half_rn(v.y) };
    __half2 h1 = { __float2half_rn(v.z), __float2half_rn(v.w) };
    ((__half2*)g_Xc)[i * 2]     = h0;
    ((__half2*)g_Xc)[i * 2 + 1] = h1;
}
__global__ void prep_wu(const float* __restrict__ W1,
                        const float* __restrict__ Wa1, const float* __restrict__ Wa2) {
    int i = blockIdx.x * 256 + threadIdx.x;       // 0 .. 3072*512-1
    int n = i >> 9, d = i & 511;
    float v;
    if (n < FF) {
        v = W1[d * FF + n];
    } else {
        int c = n - FF;                            // 0..1023
        const float* Wa = (c >> 9) ? Wa2 : Wa1;    // [E,D,H]
        int cc = c & 511;
        v = Wa[((cc >> 6) * DD + d) * 64 + (cc & 63)];
    }
    g_Wu[i] = __float2half_rn(v);
}
__global__ void prep_wd(const float* __restrict__ W2,
                        const float* __restrict__ Wb1, const float* __restrict__ Wb2) {
    int i = blockIdx.x * 256 + threadIdx.x;       // 0 .. 512*3072-1
    int d = i / NUP, k = i % NUP;
    float v;
    if (k < FF) {
        v = W2[k * DD + d];
    } else {
        int j = k - FF;                            // 0..1023
        const float* Wb = (j >> 9) ? Wb2 : Wb1;    // flat [512,512]
        v = Wb[(j & 511) * DD + d];
    }
    g_Wd[i] = __float2half_rn(v);
}

// ---------------------------------------------------------------------------
// Gating v2: smem-staged Wg, conflict-free LDS.128, coalesced x reads.
// 8 warps/block, one token per warp. Wg_s row stride 20 floats (80B).
// ---------------------------------------------------------------------------
__device__ __forceinline__ void write_top2(const float* a, float* o) {
    int i0 = 0; float v0 = a[0];
#pragma unroll
    for (int e = 1; e < 8; e++) if (a[e] > v0) { v0 = a[e]; i0 = e; }
    int i1 = -1; float v1 = -3.4e38f;
#pragma unroll
    for (int e = 0; e < 8; e++) if (e != i0 && a[e] > v1) { v1 = a[e]; i1 = e; }
    float t = expf(v1 - v0);
    float inv = 1.0f / (1.0f + t);
#pragma unroll
    for (int e = 0; e < 8; e++) o[e] = 0.0f;
    o[i0] = inv;
    o[i1] = t * inv;
}

__global__ __launch_bounds__(256)
void gate_kernel(const float* __restrict__ x,
                 const float* __restrict__ Wg1,
                 const float* __restrict__ Wg2) {
    __shared__ float Wg_s[DD * 20];                 // [j][0..15], stride 20 (40KB)
    const int tid  = threadIdx.x;
    const int wid  = tid >> 5;
    const int lane = tid & 31;

    // Cooperative stage: 2048 float4 reads (Wg1 then Wg2), 8 per thread
#pragma unroll
    for (int i = 0; i < 8; i++) {
        int v = tid + i * 256;                      // 0..2047
        int layer = v >> 10, rem = v & 1023;
        int j = rem >> 1, e4 = rem & 1;
        float4 w = ((const float4*)(layer ? Wg2 : Wg1))[(size_t)j * 2 + e4];
        *(float4*)&Wg_s[j * 20 + layer * 8 + e4 * 4] = w;
    }
    __syncthreads();

    const int tok = blockIdx.x * 8 + wid;
    const float* xr = x + (size_t)tok * DD;

    float4 acc0 = {0,0,0,0}, acc1 = {0,0,0,0};      // layer1 e0..7
    float4 acc2 = {0,0,0,0}, acc3 = {0,0,0,0};      // layer2 e0..7
#pragma unroll
    for (int q = 0; q < 16; q++) {
        int j = q * 32 + lane;
        float xv = xr[j];                           // coalesced 128B per warp
        const float4* wrow = (const float4*)&Wg_s[j * 20];
        float4 w0 = wrow[0], w1 = wrow[1], w2 = wrow[2], w3 = wrow[3];
        acc0.x = fmaf(xv, w0.x, acc0.x); acc0.y = fmaf(xv, w0.y, acc0.y);
        acc0.z = fmaf(xv, w0.z, acc0.z); acc0.w = fmaf(xv, w0.w, acc0.w);
        acc1.x = fmaf(xv, w1.x, acc1.x); acc1.y = fmaf(xv, w1.y, acc1.y);
        acc1.z = fmaf(xv, w1.z, acc1.z); acc1.w = fmaf(xv, w1.w, acc1.w);
        acc2.x = fmaf(xv, w2.x, acc2.x); acc2.y = fmaf(xv, w2.y, acc2.y);
        acc2.z = fmaf(xv, w2.z, acc2.z); acc2.w = fmaf(xv, w2.w, acc2.w);
        acc3.x = fmaf(xv, w3.x, acc3.x); acc3.y = fmaf(xv, w3.y, acc3.y);
        acc3.z = fmaf(xv, w3.z, acc3.z); acc3.w = fmaf(xv, w3.w, acc3.w);
    }

    float a[16] = { acc0.x, acc0.y, acc0.z, acc0.w, acc1.x, acc1.y, acc1.z, acc1.w,
                    acc2.x, acc2.y, acc2.z, acc2.w, acc3.x, acc3.y, acc3.z, acc3.w };
#pragma unroll
    for (int e = 0; e < 16; e++) {
#pragma unroll
        for (int o = 16; o; o >>= 1)
            a[e] += __shfl_xor_sync(0xffffffffu, a[e], o);
    }
    if (lane == 0) {
        write_top2(a,     &g_w[tok * 16]);
        write_top2(a + 8, &g_w[tok * 16 + 8]);
    }
}

// ===========================================================================
// Shared GEMM machinery: 128x128 tile, BK=64, XOR-swizzled smem, 3-stage
// cp.async, 256 threads, 2 CTAs/SM. 8 warps (2x4); each warp 64x32.
// ===========================================================================
#define KOFF(ks, lane) ((unsigned)((((ks) * 2 + ((lane) >> 4)) ^ ((lane) & 7)) << 4))

struct Frag { float acc[4][4][4]; };

template <typename LoadA>
__device__ __forceinline__ void gemm_core(
    Frag& F, unsigned smb, int tid, int lane, int m0, int n0, int KT,
    LoadA srcA, const __half* __restrict__ Bt, int ldb, int col0)
{
    auto load_stage = [&](int st, int k0) {
        unsigned base = smb + (unsigned)(st * STG_BYTES);
#pragma unroll
        for (int i = 0; i < 8; i++) {
            int cid = tid + i * 256;                 // 0..2047
            int row = cid >> 3, c = cid & 7;         // 8 x 16B per 128B row
            unsigned dst = base + (unsigned)(row * ROWB + ((c ^ (row & 7)) << 4));
            const __half* src = (row < BM)
                ? srcA(row, k0 + c * 8)
                : Bt + (size_t)(col0 + row - BM) * ldb + k0 + c * 8;
            cp16(dst, src);
        }
        asm volatile("cp.async.commit_group;" ::: "memory");
    };

    const unsigned arow = (unsigned)((m0 + (lane & 15)) * ROWB);
    const unsigned brow = (unsigned)((BM + n0 + (lane & 15)) * ROWB);

    load_stage(0, 0);
    load_stage(1, BK);

#pragma unroll 1
    for (int kt = 0; kt < KT; kt++) {
        if (kt + 2 < KT) {
            load_stage((kt + 2) % NSTG, (kt + 2) * BK);
            asm volatile("cp.async.wait_group 2;" ::: "memory");
        } else if (kt + 1 < KT) {
            asm volatile("cp.async.wait_group 1;" ::: "memory");
        } else {
            asm volatile("cp.async.wait_group 0;" ::: "memory");
        }
        __syncthreads();

        const unsigned sbase = smb + (unsigned)((kt % NSTG) * STG_BYTES);
#pragma unroll
        for (int ks = 0; ks < 4; ks++) {
            const unsigned koff = KOFF(ks, lane);
            unsigned a[4][4];
#pragma unroll
            for (int mt = 0; mt < 4; mt++)
                ldsm4(a[mt][0], a[mt][1], a[mt][2], a[mt][3],
                      sbase + arow + (unsigned)(mt * 16 * ROWB) + koff);
            unsigned b[4][2];
#pragma unroll
            for (int np = 0; np < 2; np++) {
                unsigned r0, r1, r2, r3;
                ldsm4(r0, r1, r2, r3,
                      sbase + brow + (unsigned)(np * 16 * ROWB) + koff);
                b[2*np][0]   = r0; b[2*np][1]   = r2;
                b[2*np+1][0] = r1; b[2*np+1][1] = r3;
            }
#pragma unroll
            for (int mt = 0; mt < 4; mt++)
#pragma unroll
                for (int nt = 0; nt < 4; nt++)
                    mma_f16(F.acc[mt][nt], a[mt], b[nt]);
        }
        __syncthreads();
    }
}

// ---------------------------------------------------------------------------
// Fused up-GEMM: g_H[:, :3072] = { gelu(x@W1+b1) | mask*w*gelu(x@Wa) }
// ---------------------------------------------------------------------------
__global__ __launch_bounds__(256, 2)
void gemm_up(const __half* __restrict__ A, const float* __restrict__ b1,
             const int* __restrict__ idp)
{
    const int col0 = blockIdx.x * BN;
    const int row0 = blockIdx.y * BM;
    const bool moe = (col0 >= FF);
    const int idv = *idp;
    if (moe && (row0 & (SS - 1)) + BM - 1 < idv) return;   // fully masked MoE tile

    extern __shared__ __half sm[];
    const unsigned smb = (unsigned)__cvta_generic_to_shared(sm);
    const int tid = threadIdx.x, wid = tid >> 5, lane = tid & 31;
    const int m0 = (wid >> 2) * 64, n0 = (wid & 3) * 32;

    Frag F;
#pragma unroll
    for (int i = 0; i < 4; i++)
#pragma unroll
        for (int j = 0; j < 4; j++)
#pragma unroll
            for (int r = 0; r < 4; r++) F.acc[i][j][r] = 0.0f;

    auto srcA = [&](int row, int k) { return A + (size_t)(row0 + row) * DD + k; };
    gemm_core(F, smb, tid, lane, m0, n0, DD / BK, srcA, g_Wu, DD, col0);

    const int g = lane >> 2, t = lane & 3;
#pragma unroll
    for (int mt = 0; mt < 4; mt++) {
#pragma unroll
        for (int nt = 0; nt < 4; nt++) {
            int r0 = row0 + m0 + mt * 16 + g;
            int r1 = r0 + 8;
            int c  = col0 + n0 + nt * 8 + 2 * t;
            float v00 = F.acc[mt][nt][0], v01 = F.acc[mt][nt][1];
            float v10 = F.acc[mt][nt][2], v11 = F.acc[mt][nt][3];
            __half2 o0, o1;
            if (!moe) {
                float2 bb = *(const float2*)(b1 + c);
                o0 = { __float2half_rn(gelu_f(v00 + bb.x)), __float2half_rn(gelu_f(v01 + bb.y)) };
                o1 = { __float2half_rn(gelu_f(v10 + bb.x)), __float2half_rn(gelu_f(v11 + bb.y)) };
            } else {
                bool a0 = ((r0 & (SS - 1)) >= idv);
                bool a1 = ((r1 & (SS - 1)) >= idv);
                int e = (c - FF) >> 6;                 // 0..15
                float w0 = a0 ? g_w[r0 * 16 + e] : 0.0f;
                float w1 = a1 ? g_w[r1 * 16 + e] : 0.0f;
                o0 = { __float2half_rn(a0 ? gelu_f(v00) * w0 : 0.0f),
                       __float2half_rn(a0 ? gelu_f(v01) * w0 : 0.0f) };
                o1 = { __float2half_rn(a1 ? gelu_f(v10) * w1 : 0.0f),
                       __float2half_rn(a1 ? gelu_f(v11) * w1 : 0.0f) };
            }
            *(__half2*)(g_H + (size_t)r0 * NUP + c) = o0;
            *(__half2*)(g_H + (size_t)r1 * NUP + c) = o1;
        }
    }
}

// ---------------------------------------------------------------------------
// Fused down-GEMM: out = g_H @ [W2t;Wbt]^T + b2.
// Fully-masked row tiles use K=2048; others K=3072.
// ---------------------------------------------------------------------------
__global__ __launch_bounds__(256, 2)
void gemm_down(const float* __restrict__ b2, float* __restrict__ out,
               const int* __restrict__ idp)
{
    const int col0 = blockIdx.x * BN;
    const int row0 = blockIdx.y * BM;
    const int idv = *idp;
    const bool fully_masked = ((row0 & (SS - 1)) + BM - 1 < idv);
    const int KT = (fully_masked ? FF : NUP) / BK;

    extern __shared__ __half sm[];
    const unsigned smb = (unsigned)__cvta_generic_to_shared(sm);
    const int tid = threadIdx.x, wid = tid >> 5, lane = tid & 31;
    const int m0 = (wid >> 2) * 64, n0 = (wid & 3) * 32;

    Frag F;
#pragma unroll
    for (int i = 0; i < 4; i++)
#pragma unroll
        for (int j = 0; j < 4; j++)
#pragma unroll
            for (int r = 0; r < 4; r++) F.acc[i][j][r] = 0.0f;

    auto srcA = [&](int row, int k) { return g_H + (size_t)(row0 + row) * NUP + k; };
    gemm_core(F, smb, tid, lane, m0, n0, KT, srcA, g_Wd, NUP, col0);

    const int g = lane >> 2, t = lane & 3;
#pragma unroll
    for (int mt = 0; mt < 4; mt++) {
#pragma unroll
        for (int nt = 0; nt < 4; nt++) {
            int r0 = row0 + m0 + mt * 16 + g;
            int r1 = r0 + 8;
            int c  = col0 + n0 + nt * 8 + 2 * t;
            float2 bb = *(const float2*)(b2 + c);
            float2 o0 = { F.acc[mt][nt][0] + bb.x, F.acc[mt][nt][1] + bb.y };
            float2 o1 = { F.acc[mt][nt][2] + bb.x, F.acc[mt][nt][3] + bb.y };
            *(float2*)(out + (size_t)r0 * DD + c) = o0;
            *(float2*)(out + (size_t)r1 * DD + c) = o1;
        }
    }
}

// ---------------------------------------------------------------------------
extern "C" void kernel_launch(void* const* d_in, const int* in_sizes, int n_in,
                              void* d_out, int out_size) {
    const float* x   = (const float*)d_in[0];
    const int*   idp = (const int*)  d_in[1];
    const float* W1  = (const float*)d_in[2];
    const float* b1  = (const float*)d_in[3];
    const float* W2  = (const float*)d_in[4];
    const float* b2  = (const float*)d_in[5];
    const float* Wg1 = (const float*)d_in[6];
    const float* Wa1 = (const float*)d_in[7];
    const float* Wb1 = (const float*)d_in[8];
    const float* Wg2 = (const float*)d_in[9];
    const float* Wa2 = (const float*)d_in[10];
    const float* Wb2 = (const float*)d_in[11];
    float* out = (float*)d_out;
    (void)in_sizes; (void)n_in; (void)out_size;

    __half* Xc;
    cudaGetSymbolAddress((void**)&Xc, g_Xc);

    cudaFuncSetAttribute(gemm_up,   cudaFuncAttributeMaxDynamicSharedMemorySize, SMEM_BYTES);
    cudaFuncSetAttribute(gemm_down, cudaFuncAttributeMaxDynamicSharedMemorySize, SMEM_BYTES);

    // Prep: fp16 conversion + stacked repacks + gating
    prep_x <<<(TT * (DD / 4)) / 256, 256>>>(x);
    prep_wu<<<NUP * DD / 256, 256>>>(W1, Wa1, Wa2);
    prep_wd<<<DD * NUP / 256, 256>>>(W2, Wb1, Wb2);
    gate_kernel<<<TT / 8, 256>>>(x, Wg1, Wg2);

    // Fused up-projection (FFN1 + both MoE up layers)
    gemm_up<<<dim3(NUP / BN, TT / BM), 256, SMEM_BYTES>>>(Xc, b1, idp);

    // Fused down-projection (FFN2 + both MoE down layers, single out write)
    gemm_down<<<dim3(DD / BN, TT / BM), 256, SMEM_BYTES>>>(b2, out, idp);
}

// round 10
// speedup vs baseline: 2.3583x; 1.0502x over previous
#include <cuda_runtime.h>
#include <cuda_fp16.h>

#define TT 32768      // B*S tokens
#define SS 8192       // sequence length
#define DD 512        // model dim
#define FF 2048       // ffn hidden
#define NMOE 1024     // concatenated MoE hidden (2 layers * E*H)
#define NUP (FF + NMOE)   // 3072 fused up-projection width

#define BM 128
#define BN 128
#define BK 64                              // halves per K-chunk (128B rows)
#define NSTG 3
#define ROWB 128                           // bytes per smem row
#define STG_BYTES ((BM + BN) * ROWB)       // 32768
#define SMEM_BYTES (NSTG * STG_BYTES)      // 98304

// Scratch (device globals; no allocation allowed)
__device__ __half g_H[(unsigned long long)TT * NUP];   // [H1 | Hm] fused hidden
__device__ __half g_Xc[(unsigned long long)TT * DD];   // fp16 x
__device__ __half g_Wu[NUP * DD];    // stacked up weights   [3072,512] K-major
__device__ __half g_Wd[DD * NUP];    // stacked down weights [512,3072] K-major
__device__ float  g_w[TT * 16];      // dense gate weights

__device__ __forceinline__ float gelu_f(float x) {
    float x3 = x * x * x;
    float t = tanhf(0.7978845608028654f * (x + 0.044715f * x3));
    return 0.5f * x * (1.0f + t);
}
__device__ __forceinline__ void cp16(unsigned dst, const void* src) {
    asm volatile("cp.async.cg.shared.global [%0], [%1], 16;" :: "r"(dst), "l"(src) : "memory");
}
__device__ __forceinline__ void ldsm4(unsigned& r0, unsigned& r1, unsigned& r2, unsigned& r3,
                                      unsigned addr) {
    asm volatile("ldmatrix.sync.aligned.m8n8.x4.shared.b16 {%0,%1,%2,%3}, [%4];"
                 : "=r"(r0), "=r"(r1), "=r"(r2), "=r"(r3) : "r"(addr));
}
__device__ __forceinline__ void mma_f16(float* c, const unsigned* a, const unsigned* b) {
    asm volatile(
        "mma.sync.aligned.m16n8k16.row.col.f32.f16.f16.f32 "
        "{%0,%1,%2,%3}, {%4,%5,%6,%7}, {%8,%9}, {%0,%1,%2,%3};"
        : "+f"(c[0]), "+f"(c[1]), "+f"(c[2]), "+f"(c[3])
        : "r"(a[0]), "r"(a[1]), "r"(a[2]), "r"(a[3]), "r"(b[0]), "r"(b[1]));
}

// ---------------------------------------------------------------------------
// Prep: stacked weight repacks (K-major fp16)
// ---------------------------------------------------------------------------
__global__ void prep_wu(const float* __restrict__ W1,
                        const float* __restrict__ Wa1, const float* __restrict__ Wa2) {
    int i = blockIdx.x * 256 + threadIdx.x;       // 0 .. 3072*512-1
    int n = i >> 9, d = i & 511;
    float v;
    if (n < FF) {
        v = W1[d * FF + n];
    } else {
        int c = n - FF;                            // 0..1023
        const float* Wa = (c >> 9) ? Wa2 : Wa1;    // [E,D,H]
        int cc = c & 511;
        v = Wa[((cc >> 6) * DD + d) * 64 + (cc & 63)];
    }
    g_Wu[i] = __float2half_rn(v);
}
__global__ void prep_wd(const float* __restrict__ W2,
                        const float* __restrict__ Wb1, const float* __restrict__ Wb2) {
    int i = blockIdx.x * 256 + threadIdx.x;       // 0 .. 512*3072-1
    int d = i / NUP, k = i % NUP;
    float v;
    if (k < FF) {
        v = W2[k * DD + d];
    } else {
        int j = k - FF;                            // 0..1023
        const float* Wb = (j >> 9) ? Wb2 : Wb1;    // flat [512,512]
        v = Wb[(j & 511) * DD + d];
    }
    g_Wd[i] = __float2half_rn(v);
}

// ---------------------------------------------------------------------------
// Gating v3: 4 tokens per warp (amortizes Wg smem reads 4x), fused x->fp16
// conversion. 8 warps/block -> 32 tokens/block; grid = TT/32.
// Wg_s row stride 20 floats (80B) keeps LDS.128 conflict-free.
// ---------------------------------------------------------------------------
__device__ __forceinline__ void write_top2(const float* a, float* o) {
    int i0 = 0; float v0 = a[0];
#pragma unroll
    for (int e = 1; e < 8; e++) if (a[e] > v0) { v0 = a[e]; i0 = e; }
    int i1 = -1; float v1 = -3.4e38f;
#pragma unroll
    for (int e = 0; e < 8; e++) if (e != i0 && a[e] > v1) { v1 = a[e]; i1 = e; }
    float t = expf(v1 - v0);
    float inv = 1.0f / (1.0f + t);
#pragma unroll
    for (int e = 0; e < 8; e++) o[e] = 0.0f;
    o[i0] = inv;
    o[i1] = t * inv;
}

__global__ __launch_bounds__(256)
void gate_kernel(const float* __restrict__ x,
                 const float* __restrict__ Wg1,
                 const float* __restrict__ Wg2) {
    __shared__ float Wg_s[DD * 20];                 // [j][0..15], stride 20 (40KB)
    const int tid  = threadIdx.x;
    const int wid  = tid >> 5;
    const int lane = tid & 31;

    // Cooperative stage: 2048 float4 reads (Wg1 then Wg2), 8 per thread
#pragma unroll
    for (int i = 0; i < 8; i++) {
        int v = tid + i * 256;                      // 0..2047
        int layer = v >> 10, rem = v & 1023;
        int j = rem >> 1, e4 = rem & 1;
        float4 w = ((const float4*)(layer ? Wg2 : Wg1))[(size_t)j * 2 + e4];
        *(float4*)&Wg_s[j * 20 + layer * 8 + e4 * 4] = w;
    }
    __syncthreads();

    const int tok0 = blockIdx.x * 32 + wid * 4;

    float acc[4][16];
#pragma unroll
    for (int p = 0; p < 4; p++)
#pragma unroll
        for (int e = 0; e < 16; e++) acc[p][e] = 0.0f;

#pragma unroll
    for (int q = 0; q < 16; q++) {
        int j = q * 32 + lane;
        const float4* wrow = (const float4*)&Wg_s[j * 20];
        float4 w0 = wrow[0], w1 = wrow[1], w2 = wrow[2], w3 = wrow[3];
        float wv[16] = { w0.x, w0.y, w0.z, w0.w, w1.x, w1.y, w1.z, w1.w,
                         w2.x, w2.y, w2.z, w2.w, w3.x, w3.y, w3.z, w3.w };
#pragma unroll
        for (int p = 0; p < 4; p++) {
            float xv = x[(size_t)(tok0 + p) * DD + j];          // coalesced
            g_Xc[(size_t)(tok0 + p) * DD + j] = __float2half_rn(xv);
#pragma unroll
            for (int e = 0; e < 16; e++)
                acc[p][e] = fmaf(xv, wv[e], acc[p][e]);
        }
    }

#pragma unroll
    for (int p = 0; p < 4; p++)
#pragma unroll
        for (int e = 0; e < 16; e++)
#pragma unroll
            for (int o = 16; o; o >>= 1)
                acc[p][e] += __shfl_xor_sync(0xffffffffu, acc[p][e], o);

#pragma unroll
    for (int p = 0; p < 4; p++) {
        if (lane == p) {
            write_top2(acc[p],     &g_w[(tok0 + p) * 16]);
            write_top2(acc[p] + 8, &g_w[(tok0 + p) * 16 + 8]);
        }
    }
}

// ===========================================================================
// Shared GEMM machinery: 128x128 tile, BK=64, XOR-swizzled smem, 3-stage
// cp.async, 256 threads, 2 CTAs/SM. 8 warps (2x4); each warp 64x32.
// ===========================================================================
#define KOFF(ks, lane) ((unsigned)((((ks) * 2 + ((lane) >> 4)) ^ ((lane) & 7)) << 4))

struct Frag { float acc[4][4][4]; };

template <typename LoadA>
__device__ __forceinline__ void gemm_core(
    Frag& F, unsigned smb, int tid, int lane, int m0, int n0, int KT,
    LoadA srcA, const __half* __restrict__ Bt, int ldb, int col0)
{
    auto load_stage = [&](int st, int k0) {
        unsigned base = smb + (unsigned)(st * STG_BYTES);
#pragma unroll
        for (int i = 0; i < 8; i++) {
            int cid = tid + i * 256;                 // 0..2047
            int row = cid >> 3, c = cid & 7;         // 8 x 16B per 128B row
            unsigned dst = base + (unsigned)(row * ROWB + ((c ^ (row & 7)) << 4));
            const __half* src = (row < BM)
                ? srcA(row, k0 + c * 8)
                : Bt + (size_t)(col0 + row - BM) * ldb + k0 + c * 8;
            cp16(dst, src);
        }
        asm volatile("cp.async.commit_group;" ::: "memory");
    };

    const unsigned arow = (unsigned)((m0 + (lane & 15)) * ROWB);
    const unsigned brow = (unsigned)((BM + n0 + (lane & 15)) * ROWB);

    load_stage(0, 0);
    load_stage(1, BK);

#pragma unroll 1
    for (int kt = 0; kt < KT; kt++) {
        if (kt + 2 < KT) {
            load_stage((kt + 2) % NSTG, (kt + 2) * BK);
            asm volatile("cp.async.wait_group 2;" ::: "memory");
        } else if (kt + 1 < KT) {
            asm volatile("cp.async.wait_group 1;" ::: "memory");
        } else {
            asm volatile("cp.async.wait_group 0;" ::: "memory");
        }
        __syncthreads();

        const unsigned sbase = smb + (unsigned)((kt % NSTG) * STG_BYTES);
#pragma unroll
        for (int ks = 0; ks < 4; ks++) {
            const unsigned koff = KOFF(ks, lane);
            unsigned a[4][4];
#pragma unroll
            for (int mt = 0; mt < 4; mt++)
                ldsm4(a[mt][0], a[mt][1], a[mt][2], a[mt][3],
                      sbase + arow + (unsigned)(mt * 16 * ROWB) + koff);
            unsigned b[4][2];
#pragma unroll
            for (int np = 0; np < 2; np++) {
                unsigned r0, r1, r2, r3;
                ldsm4(r0, r1, r2, r3,
                      sbase + brow + (unsigned)(np * 16 * ROWB) + koff);
                b[2*np][0]   = r0; b[2*np][1]   = r2;
                b[2*np+1][0] = r1; b[2*np+1][1] = r3;
            }
#pragma unroll
            for (int mt = 0; mt < 4; mt++)
#pragma unroll
                for (int nt = 0; nt < 4; nt++)
                    mma_f16(F.acc[mt][nt], a[mt], b[nt]);
        }
        __syncthreads();
    }
}

// ---------------------------------------------------------------------------
// Fused up-GEMM: g_H[:, :3072] = { gelu(x@W1+b1) | mask*w*gelu(x@Wa) }
// ---------------------------------------------------------------------------
__global__ __launch_bounds__(256, 2)
void gemm_up(const __half* __restrict__ A, const float* __restrict__ b1,
             const int* __restrict__ idp)
{
    const int col0 = blockIdx.x * BN;
    const int row0 = blockIdx.y * BM;
    const bool moe = (col0 >= FF);
    const int idv = *idp;
    if (moe && (row0 & (SS - 1)) + BM - 1 < idv) return;   // fully masked MoE tile

    extern __shared__ __half sm[];
    const unsigned smb = (unsigned)__cvta_generic_to_shared(sm);
    const int tid = threadIdx.x, wid = tid >> 5, lane = tid & 31;
    const int m0 = (wid >> 2) * 64, n0 = (wid & 3) * 32;

    Frag F;
#pragma unroll
    for (int i = 0; i < 4; i++)
#pragma unroll
        for (int j = 0; j < 4; j++)
#pragma unroll
            for (int r = 0; r < 4; r++) F.acc[i][j][r] = 0.0f;

    auto srcA = [&](int row, int k) { return A + (size_t)(row0 + row) * DD + k; };
    gemm_core(F, smb, tid, lane, m0, n0, DD / BK, srcA, g_Wu, DD, col0);

    const int g = lane >> 2, t = lane & 3;
#pragma unroll
    for (int mt = 0; mt < 4; mt++) {
#pragma unroll
        for (int nt = 0; nt < 4; nt++) {
            int r0 = row0 + m0 + mt * 16 + g;
            int r1 = r0 + 8;
            int c  = col0 + n0 + nt * 8 + 2 * t;
            float v00 = F.acc[mt][nt][0], v01 = F.acc[mt][nt][1];
            float v10 = F.acc[mt][nt][2], v11 = F.acc[mt][nt][3];
            __half2 o0, o1;
            if (!moe) {
                float2 bb = *(const float2*)(b1 + c);
                o0 = { __float2half_rn(gelu_f(v00 + bb.x)), __float2half_rn(gelu_f(v01 + bb.y)) };
                o1 = { __float2half_rn(gelu_f(v10 + bb.x)), __float2half_rn(gelu_f(v11 + bb.y)) };
            } else {
                bool a0 = ((r0 & (SS - 1)) >= idv);
                bool a1 = ((r1 & (SS - 1)) >= idv);
                int e = (c - FF) >> 6;                 // 0..15
                float w0 = a0 ? g_w[r0 * 16 + e] : 0.0f;
                float w1 = a1 ? g_w[r1 * 16 + e] : 0.0f;
                o0 = { __float2half_rn(a0 ? gelu_f(v00) * w0 : 0.0f),
                       __float2half_rn(a0 ? gelu_f(v01) * w0 : 0.0f) };
                o1 = { __float2half_rn(a1 ? gelu_f(v10) * w1 : 0.0f),
                       __float2half_rn(a1 ? gelu_f(v11) * w1 : 0.0f) };
            }
            *(__half2*)(g_H + (size_t)r0 * NUP + c) = o0;
            *(__half2*)(g_H + (size_t)r1 * NUP + c) = o1;
        }
    }
}

// ---------------------------------------------------------------------------
// Fused down-GEMM: out = g_H @ [W2t;Wbt]^T + b2.
// Fully-masked row tiles use K=2048; others K=3072.
// ---------------------------------------------------------------------------
__global__ __launch_bounds__(256, 2)
void gemm_down(const float* __restrict__ b2, float* __restrict__ out,
               const int* __restrict__ idp)
{
    const int col0 = blockIdx.x * BN;
    const int row0 = blockIdx.y * BM;
    const int idv = *idp;
    const bool fully_masked = ((row0 & (SS - 1)) + BM - 1 < idv);
    const int KT = (fully_masked ? FF : NUP) / BK;

    extern __shared__ __half sm[];
    const unsigned smb = (unsigned)__cvta_generic_to_shared(sm);
    const int tid = threadIdx.x, wid = tid >> 5, lane = tid & 31;
    const int m0 = (wid >> 2) * 64, n0 = (wid & 3) * 32;

    Frag F;
#pragma unroll
    for (int i = 0; i < 4; i++)
#pragma unroll
        for (int j = 0; j < 4; j++)
#pragma unroll
            for (int r = 0; r < 4; r++) F.acc[i][j][r] = 0.0f;

    auto srcA = [&](int row, int k) { return g_H + (size_t)(row0 + row) * NUP + k; };
    gemm_core(F, smb, tid, lane, m0, n0, KT, srcA, g_Wd, NUP, col0);

    const int g = lane >> 2, t = lane & 3;
#pragma unroll
    for (int mt = 0; mt < 4; mt++) {
#pragma unroll
        for (int nt = 0; nt < 4; nt++) {
            int r0 = row0 + m0 + mt * 16 + g;
            int r1 = r0 + 8;
            int c  = col0 + n0 + nt * 8 + 2 * t;
            float2 bb = *(const float2*)(b2 + c);
            float2 o0 = { F.acc[mt][nt][0] + bb.x, F.acc[mt][nt][1] + bb.y };
            float2 o1 = { F.acc[mt][nt][2] + bb.x, F.acc[mt][nt][3] + bb.y };
            *(float2*)(out + (size_t)r0 * DD + c) = o0;
            *(float2*)(out + (size_t)r1 * DD + c) = o1;
        }
    }
}

// ---------------------------------------------------------------------------
extern "C" void kernel_launch(void* const* d_in, const int* in_sizes, int n_in,
                              void* d_out, int out_size) {
    const float* x   = (const float*)d_in[0];
    const int*   idp = (const int*)  d_in[1];
    const float* W1  = (const float*)d_in[2];
    const float* b1  = (const float*)d_in[3];
    const float* W2  = (const float*)d_in[4];
    const float* b2  = (const float*)d_in[5];
    const float* Wg1 = (const float*)d_in[6];
    const float* Wa1 = (const float*)d_in[7];
    const float* Wb1 = (const float*)d_in[8];
    const float* Wg2 = (const float*)d_in[9];
    const float* Wa2 = (const float*)d_in[10];
    const float* Wb2 = (const float*)d_in[11];
    float* out = (float*)d_out;
    (void)in_sizes; (void)n_in; (void)out_size;

    __half* Xc;
    cudaGetSymbolAddress((void**)&Xc, g_Xc);

    cudaFuncSetAttribute(gemm_up,   cudaFuncAttributeMaxDynamicSharedMemorySize, SMEM_BYTES);
    cudaFuncSetAttribute(gemm_down, cudaFuncAttributeMaxDynamicSharedMemorySize, SMEM_BYTES);

    // Prep: stacked repacks + gating (gate also emits fp16 x)
    prep_wu<<<NUP * DD / 256, 256>>>(W1, Wa1, Wa2);
    prep_wd<<<DD * NUP / 256, 256>>>(W2, Wb1, Wb2);
    gate_kernel<<<TT / 32, 256>>>(x, Wg1, Wg2);

    // Fused up-projection (FFN1 + both MoE up layers)
    gemm_up<<<dim3(NUP / BN, TT / BM), 256, SMEM_BYTES>>>(Xc, b1, idp);

    // Fused down-projection (FFN2 + both MoE down layers, single out write)
    gemm_down<<<dim3(DD / BN, TT / BM), 256, SMEM_BYTES>>>(b2, out, idp);
}

// round 11
// speedup vs baseline: 2.4251x; 1.0283x over previous
#include <cuda_runtime.h>
#include <cuda_fp16.h>

#define TT 32768      // B*S tokens
#define SS 8192       // sequence length
#define DD 512        // model dim
#define FF 2048       // ffn hidden
#define NMOE 1024     // concatenated MoE hidden (2 layers * E*H)
#define NUP (FF + NMOE)   // 3072 fused up-projection width

#define BM 128
#define BN 128
#define BK 64                              // halves per K-chunk (128B rows)
#define NSTG 3
#define ROWB 128                           // bytes per smem row
#define STG_BYTES ((BM + BN) * ROWB)       // 32768
#define SMEM_BYTES (NSTG * STG_BYTES)      // 98304

// Scratch (device globals; no allocation allowed)
__device__ __half g_H[(unsigned long long)TT * NUP];   // [H1 | Hm] fused hidden
__device__ __half g_Xc[(unsigned long long)TT * DD];   // fp16 x
__device__ __half g_Wu[NUP * DD];    // stacked up weights   [3072,512] K-major
__device__ __half g_Wd[DD * NUP];    // stacked down weights [512,3072] K-major
__device__ float  g_w[TT * 16];      // dense gate weights

__device__ __forceinline__ float gelu_f(float x) {
    float x3 = x * x * x;
    float t = tanhf(0.7978845608028654f * (x + 0.044715f * x3));
    return 0.5f * x * (1.0f + t);
}
__device__ __forceinline__ void cp16(unsigned dst, const void* src) {
    asm volatile("cp.async.cg.shared.global [%0], [%1], 16;" :: "r"(dst), "l"(src) : "memory");
}
__device__ __forceinline__ void ldsm4(unsigned& r0, unsigned& r1, unsigned& r2, unsigned& r3,
                                      unsigned addr) {
    asm volatile("ldmatrix.sync.aligned.m8n8.x4.shared.b16 {%0,%1,%2,%3}, [%4];"
                 : "=r"(r0), "=r"(r1), "=r"(r2), "=r"(r3) : "r"(addr));
}
__device__ __forceinline__ void mma_f16(float* c, const unsigned* a, const unsigned* b) {
    asm volatile(
        "mma.sync.aligned.m16n8k16.row.col.f32.f16.f16.f32 "
        "{%0,%1,%2,%3}, {%4,%5,%6,%7}, {%8,%9}, {%0,%1,%2,%3};"
        : "+f"(c[0]), "+f"(c[1]), "+f"(c[2]), "+f"(c[3])
        : "r"(a[0]), "r"(a[1]), "r"(a[2]), "r"(a[3]), "r"(b[0]), "r"(b[1]));
}

// ---------------------------------------------------------------------------
// Prep: stacked weight repacks (K-major fp16)
// ---------------------------------------------------------------------------
__global__ void prep_wu(const float* __restrict__ W1,
                        const float* __restrict__ Wa1, const float* __restrict__ Wa2) {
    int i = blockIdx.x * 256 + threadIdx.x;       // 0 .. 3072*512-1
    int n = i >> 9, d = i & 511;
    float v;
    if (n < FF) {
        v = W1[d * FF + n];
    } else {
        int c = n - FF;                            // 0..1023
        const float* Wa = (c >> 9) ? Wa2 : Wa1;    // [E,D,H]
        int cc = c & 511;
        v = Wa[((cc >> 6) * DD + d) * 64 + (cc & 63)];
    }
    g_Wu[i] = __float2half_rn(v);
}
__global__ void prep_wd(const float* __restrict__ W2,
                        const float* __restrict__ Wb1, const float* __restrict__ Wb2) {
    int i = blockIdx.x * 256 + threadIdx.x;       // 0 .. 512*3072-1
    int d = i / NUP, k = i % NUP;
    float v;
    if (k < FF) {
        v = W2[k * DD + d];
    } else {
        int j = k - FF;                            // 0..1023
        const float* Wb = (j >> 9) ? Wb2 : Wb1;    // flat [512,512]
        v = Wb[(j & 511) * DD + d];
    }
    g_Wd[i] = __float2half_rn(v);
}

// ---------------------------------------------------------------------------
// Gating v3: 4 tokens per warp, fused x->fp16 conversion.
// ---------------------------------------------------------------------------
__device__ __forceinline__ void write_top2(const float* a, float* o) {
    int i0 = 0; float v0 = a[0];
#pragma unroll
    for (int e = 1; e < 8; e++) if (a[e] > v0) { v0 = a[e]; i0 = e; }
    int i1 = -1; float v1 = -3.4e38f;
#pragma unroll
    for (int e = 0; e < 8; e++) if (e != i0 && a[e] > v1) { v1 = a[e]; i1 = e; }
    float t = expf(v1 - v0);
    float inv = 1.0f / (1.0f + t);
#pragma unroll
    for (int e = 0; e < 8; e++) o[e] = 0.0f;
    o[i0] = inv;
    o[i1] = t * inv;
}

__global__ __launch_bounds__(256)
void gate_kernel(const float* __restrict__ x,
                 const float* __restrict__ Wg1,
                 const float* __restrict__ Wg2) {
    __shared__ float Wg_s[DD * 20];                 // [j][0..15], stride 20 (40KB)
    const int tid  = threadIdx.x;
    const int wid  = tid >> 5;
    const int lane = tid & 31;

#pragma unroll
    for (int i = 0; i < 8; i++) {
        int v = tid + i * 256;                      // 0..2047
        int layer = v >> 10, rem = v & 1023;
        int j = rem >> 1, e4 = rem & 1;
        float4 w = ((const float4*)(layer ? Wg2 : Wg1))[(size_t)j * 2 + e4];
        *(float4*)&Wg_s[j * 20 + layer * 8 + e4 * 4] = w;
    }
    __syncthreads();

    const int tok0 = blockIdx.x * 32 + wid * 4;

    float acc[4][16];
#pragma unroll
    for (int p = 0; p < 4; p++)
#pragma unroll
        for (int e = 0; e < 16; e++) acc[p][e] = 0.0f;

#pragma unroll
    for (int q = 0; q < 16; q++) {
        int j = q * 32 + lane;
        const float4* wrow = (const float4*)&Wg_s[j * 20];
        float4 w0 = wrow[0], w1 = wrow[1], w2 = wrow[2], w3 = wrow[3];
        float wv[16] = { w0.x, w0.y, w0.z, w0.w, w1.x, w1.y, w1.z, w1.w,
                         w2.x, w2.y, w2.z, w2.w, w3.x, w3.y, w3.z, w3.w };
#pragma unroll
        for (int p = 0; p < 4; p++) {
            float xv = x[(size_t)(tok0 + p) * DD + j];          // coalesced
            g_Xc[(size_t)(tok0 + p) * DD + j] = __float2half_rn(xv);
#pragma unroll
            for (int e = 0; e < 16; e++)
                acc[p][e] = fmaf(xv, wv[e], acc[p][e]);
        }
    }

#pragma unroll
    for (int p = 0; p < 4; p++)
#pragma unroll
        for (int e = 0; e < 16; e++)
#pragma unroll
            for (int o = 16; o; o >>= 1)
                acc[p][e] += __shfl_xor_sync(0xffffffffu, acc[p][e], o);

#pragma unroll
    for (int p = 0; p < 4; p++) {
        if (lane == p) {
            write_top2(acc[p],     &g_w[(tok0 + p) * 16]);
            write_top2(acc[p] + 8, &g_w[(tok0 + p) * 16 + 8]);
        }
    }
}

// ===========================================================================
// GEMM core v2: compile-time strides, hoisted addressing, ONE barrier/K-iter.
// 128x128 tile, BK=64, XOR-swizzled smem, 3-stage cp.async, 256 threads,
// 2 CTAs/SM. 8 warps (2x4); each warp 64x32.
// ===========================================================================
struct Frag { float acc[4][4][4]; };

template <int LDA, int LDB>
__device__ __forceinline__ void gemm_core(
    Frag& F, unsigned smb, int tid, int lane, int m0, int n0, int KT,
    const __half* __restrict__ A0,   // A + row0*LDA
    const __half* __restrict__ B0)   // Bt + col0*LDB
{
    // ---- hoisted cp.async addressing ----
    const int r0 = tid >> 3;                    // 0..31
    const int c  = tid & 7;                     // 16B chunk in 128B row
    const __half* pA = A0 + (size_t)r0 * LDA + c * 8;
    const __half* pB = B0 + (size_t)r0 * LDB + c * 8;
    const unsigned dstoff = (unsigned)(r0 * ROWB + (((c ^ (r0 & 7))) << 4));

    auto load_stage = [&](int st, int k0) {
        unsigned base = smb + (unsigned)(st * STG_BYTES) + dstoff;
#pragma unroll
        for (int i = 0; i < 4; i++)                       // A rows r0+32i
            cp16(base + i * 4096, pA + k0 + i * 32 * LDA);
#pragma unroll
        for (int i = 0; i < 4; i++)                       // B rows r0+32i
            cp16(base + BM * ROWB + i * 4096, pB + k0 + i * 32 * LDB);
        asm volatile("cp.async.commit_group;" ::: "memory");
    };

    // ---- hoisted ldmatrix addressing ----
    const unsigned arow = (unsigned)((m0 + (lane & 15)) * ROWB);
    const unsigned brow = (unsigned)((BM + n0 + (lane & 15)) * ROWB);
    unsigned koff[4];
#pragma unroll
    for (int ks = 0; ks < 4; ks++)
        koff[ks] = (unsigned)((((ks * 2 + (lane >> 4)) ^ (lane & 7))) << 4);

    load_stage(0, 0);
    load_stage(1, BK);

#pragma unroll 1
    for (int kt = 0; kt < KT; kt++) {
        if (kt + 1 < KT) {
            asm volatile("cp.async.wait_group 1;" ::: "memory");
        } else {
            asm volatile("cp.async.wait_group 0;" ::: "memory");
        }
        __syncthreads();                       // single barrier per K-iter
        if (kt + 2 < KT)
            load_stage((kt + 2) % NSTG, (kt + 2) * BK);

        const unsigned sbase = smb + (unsigned)((kt % NSTG) * STG_BYTES);
#pragma unroll
        for (int ks = 0; ks < 4; ks++) {
            const unsigned abase = sbase + arow + koff[ks];
            const unsigned bbase = sbase + brow + koff[ks];
            unsigned a[4][4];
#pragma unroll
            for (int mt = 0; mt < 4; mt++)
                ldsm4(a[mt][0], a[mt][1], a[mt][2], a[mt][3],
                      abase + (unsigned)(mt * 16 * ROWB));
            unsigned b[4][2];
#pragma unroll
            for (int np = 0; np < 2; np++) {
                unsigned q0, q1, q2, q3;
                ldsm4(q0, q1, q2, q3, bbase + (unsigned)(np * 16 * ROWB));
                b[2*np][0]   = q0; b[2*np][1]   = q2;
                b[2*np+1][0] = q1; b[2*np+1][1] = q3;
            }
#pragma unroll
            for (int mt = 0; mt < 4; mt++)
#pragma unroll
                for (int nt = 0; nt < 4; nt++)
                    mma_f16(F.acc[mt][nt], a[mt], b[nt]);
        }
    }
}

// ---------------------------------------------------------------------------
// Fused up-GEMM: g_H[:, :3072] = { gelu(x@W1+b1) | mask*w*gelu(x@Wa) }
// ---------------------------------------------------------------------------
__global__ __launch_bounds__(256, 2)
void gemm_up(const __half* __restrict__ A, const float* __restrict__ b1,
             const int* __restrict__ idp)
{
    const int col0 = blockIdx.x * BN;
    const int row0 = blockIdx.y * BM;
    const bool moe = (col0 >= FF);
    const int idv = *idp;
    if (moe && (row0 & (SS - 1)) + BM - 1 < idv) return;   // fully masked MoE tile

    extern __shared__ __half sm[];
    const unsigned smb = (unsigned)__cvta_generic_to_shared(sm);
    const int tid = threadIdx.x, wid = tid >> 5, lane = tid & 31;
    const int m0 = (wid >> 2) * 64, n0 = (wid & 3) * 32;

    Frag F;
#pragma unroll
    for (int i = 0; i < 4; i++)
#pragma unroll
        for (int j = 0; j < 4; j++)
#pragma unroll
            for (int r = 0; r < 4; r++) F.acc[i][j][r] = 0.0f;

    gemm_core<DD, DD>(F, smb, tid, lane, m0, n0, DD / BK,
                      A + (size_t)row0 * DD, g_Wu + (size_t)col0 * DD);

    const int g = lane >> 2, t = lane & 3;
#pragma unroll
    for (int mt = 0; mt < 4; mt++) {
#pragma unroll
        for (int nt = 0; nt < 4; nt++) {
            int r0 = row0 + m0 + mt * 16 + g;
            int r1 = r0 + 8;
            int c  = col0 + n0 + nt * 8 + 2 * t;
            float v00 = F.acc[mt][nt][0], v01 = F.acc[mt][nt][1];
            float v10 = F.acc[mt][nt][2], v11 = F.acc[mt][nt][3];
            __half2 o0, o1;
            if (!moe) {
                float2 bb = *(const float2*)(b1 + c);
                o0 = { __float2half_rn(gelu_f(v00 + bb.x)), __float2half_rn(gelu_f(v01 + bb.y)) };
                o1 = { __float2half_rn(gelu_f(v10 + bb.x)), __float2half_rn(gelu_f(v11 + bb.y)) };
            } else {
                bool a0 = ((r0 & (SS - 1)) >= idv);
                bool a1 = ((r1 & (SS - 1)) >= idv);
                int e = (c - FF) >> 6;                 // 0..15
                float w0 = a0 ? g_w[r0 * 16 + e] : 0.0f;
                float w1 = a1 ? g_w[r1 * 16 + e] : 0.0f;
                o0 = { __float2half_rn(a0 ? gelu_f(v00) * w0 : 0.0f),
                       __float2half_rn(a0 ? gelu_f(v01) * w0 : 0.0f) };
                o1 = { __float2half_rn(a1 ? gelu_f(v10) * w1 : 0.0f),
                       __float2half_rn(a1 ? gelu_f(v11) * w1 : 0.0f) };
            }
            *(__half2*)(g_H + (size_t)r0 * NUP + c) = o0;
            *(__half2*)(g_H + (size_t)r1 * NUP + c) = o1;
        }
    }
}

// ---------------------------------------------------------------------------
// Fused down-GEMM: out = g_H @ [W2t;Wbt]^T + b2.
// Fully-masked row tiles use K=2048; others K=3072.
// ---------------------------------------------------------------------------
__global__ __launch_bounds__(256, 2)
void gemm_down(const float* __restrict__ b2, float* __restrict__ out,
               const int* __restrict__ idp)
{
    const int col0 = blockIdx.x * BN;
    const int row0 = blockIdx.y * BM;
    const int idv = *idp;
    const bool fully_masked = ((row0 & (SS - 1)) + BM - 1 < idv);
    const int KT = (fully_masked ? FF : NUP) / BK;

    extern __shared__ __half sm[];
    const unsigned smb = (unsigned)__cvta_generic_to_shared(sm);
    const int tid = threadIdx.x, wid = tid >> 5, lane = tid & 31;
    const int m0 = (wid >> 2) * 64, n0 = (wid & 3) * 32;

    Frag F;
#pragma unroll
    for (int i = 0; i < 4; i++)
#pragma unroll
        for (int j = 0; j < 4; j++)
#pragma unroll
            for (int r = 0; r < 4; r++) F.acc[i][j][r] = 0.0f;

    gemm_core<NUP, NUP>(F, smb, tid, lane, m0, n0, KT,
                        g_H + (size_t)row0 * NUP, g_Wd + (size_t)col0 * NUP);

    const int g = lane >> 2, t = lane & 3;
#pragma unroll
    for (int mt = 0; mt < 4; mt++) {
#pragma unroll
        for (int nt = 0; nt < 4; nt++) {
            int r0 = row0 + m0 + mt * 16 + g;
            int r1 = r0 + 8;
            int c  = col0 + n0 + nt * 8 + 2 * t;
            float2 bb = *(const float2*)(b2 + c);
            float2 o0 = { F.acc[mt][nt][0] + bb.x, F.acc[mt][nt][1] + bb.y };
            float2 o1 = { F.acc[mt][nt][2] + bb.x, F.acc[mt][nt][3] + bb.y };
            *(float2*)(out + (size_t)r0 * DD + c) = o0;
            *(float2*)(out + (size_t)r1 * DD + c) = o1;
        }
    }
}

// ---------------------------------------------------------------------------
extern "C" void kernel_launch(void* const* d_in, const int* in_sizes, int n_in,
                              void* d_out, int out_size) {
    const float* x   = (const float*)d_in[0];
    const int*   idp = (const int*)  d_in[1];
    const float* W1  = (const float*)d_in[2];
    const float* b1  = (const float*)d_in[3];
    const float* W2  = (const float*)d_in[4];
    const float* b2  = (const float*)d_in[5];
    const float* Wg1 = (const float*)d_in[6];
    const float* Wa1 = (const float*)d_in[7];
    const float* Wb1 = (const float*)d_in[8];
    const float* Wg2 = (const float*)d_in[9];
    const float* Wa2 = (const float*)d_in[10];
    const float* Wb2 = (const float*)d_in[11];
    float* out = (float*)d_out;
    (void)in_sizes; (void)n_in; (void)out_size;

    __half* Xc;
    cudaGetSymbolAddress((void**)&Xc, g_Xc);

    cudaFuncSetAttribute(gemm_up,   cudaFuncAttributeMaxDynamicSharedMemorySize, SMEM_BYTES);
    cudaFuncSetAttribute(gemm_down, cudaFuncAttributeMaxDynamicSharedMemorySize, SMEM_BYTES);

    // Prep: stacked repacks + gating (gate also emits fp16 x)
    prep_wu<<<NUP * DD / 256, 256>>>(W1, Wa1, Wa2);
    prep_wd<<<DD * NUP / 256, 256>>>(W2, Wb1, Wb2);
    gate_kernel<<<TT / 32, 256>>>(x, Wg1, Wg2);

    // Fused up-projection (FFN1 + both MoE up layers)
    gemm_up<<<dim3(NUP / BN, TT / BM), 256, SMEM_BYTES>>>(Xc, b1, idp);

    // Fused down-projection (FFN2 + both MoE down layers, single out write)
    gemm_down<<<dim3(DD / BN, TT / BM), 256, SMEM_BYTES>>>(b2, out, idp);
}